// round 5
// baseline (speedup 1.0000x reference)
#include <cuda_runtime.h>
#include <cuda_bf16.h>
#include <cstdint>

// ---------------------------------------------------------------------------
// GCN_VCG, round 5:
//  - GEMMs: 512-thread CTAs, M=128 tiles (16 warps, 4m x 4n, warp tile 32x32),
//    persistent grid, resident weights (mlp) / resident-hi + streamed-lo
//    (update), mma.sync bf16 3-pass float split.
//  - Aggregation: CSR gather (warp per dst node).
// ---------------------------------------------------------------------------

#define D        128
#define NT       256
#define NT2      512
#define VMAX     50000
#define CMAX     210000
#define EHMAX    315000

// ------------------------- scratch (no runtime alloc) ----------------------
__device__ float g_t_pv2c[(size_t)VMAX * D];
__device__ float g_t_nv2c[(size_t)VMAX * D];
__device__ float g_t_pc2v[(size_t)CMAX * D];
__device__ float g_t_nc2v[(size_t)CMAX * D];
__device__ float g_agg_c[2][(size_t)CMAX * D];
__device__ float g_agg_v[2][(size_t)VMAX * D];
__device__ unsigned char g_wimg_mlp[4][2 * 65536];
__device__ unsigned char g_wimg_cu[3 * 65536];
__device__ unsigned char g_wimg_vu[3 * 65536];
__device__ int   g_degi_pv[VMAX], g_degi_nv[VMAX];
__device__ int   g_degi_pc[CMAX], g_degi_nc[CMAX];
__device__ int   g_rp_pc[CMAX + 1], g_rp_nc[CMAX + 1];
__device__ int   g_rp_pv[VMAX + 1], g_rp_nv[VMAX + 1];
__device__ int   g_fl_pc[CMAX], g_fl_nc[CMAX], g_fl_pv[VMAX], g_fl_nv[VMAX];
__device__ int   g_sl_pc_src[EHMAX], g_sl_nc_src[EHMAX];
__device__ int   g_sl_pv_src[EHMAX], g_sl_nv_src[EHMAX];
__device__ float g_sl_pc_w[EHMAX], g_sl_nc_w[EHMAX];
__device__ float g_sl_pv_w[EHMAX], g_sl_nv_w[EHMAX];

// ------------------------------ helpers ------------------------------------
__device__ __forceinline__ uint32_t smem_u32(const void* p) {
    uint32_t a;
    asm("{ .reg .u64 t; cvta.to.shared.u64 t, %1; cvt.u32.u64 %0, t; }"
        : "=r"(a) : "l"(p));
    return a;
}

__device__ __host__ __forceinline__ uint32_t swz(int r, int c) {
    return ((uint32_t)r << 8) + ((uint32_t)(((c >> 3) ^ (r & 7)) & 15) << 4)
         + ((uint32_t)(c & 7) << 1);
}

__device__ __forceinline__ void split2(float a, float b, uint32_t& hi, uint32_t& lo) {
    __nv_bfloat16 ha = __float2bfloat16(a);
    __nv_bfloat16 hb = __float2bfloat16(b);
    __nv_bfloat16 la = __float2bfloat16(a - __bfloat162float(ha));
    __nv_bfloat16 lb = __float2bfloat16(b - __bfloat162float(hb));
    hi = (uint32_t)__bfloat16_as_ushort(ha) | ((uint32_t)__bfloat16_as_ushort(hb) << 16);
    lo = (uint32_t)__bfloat16_as_ushort(la) | ((uint32_t)__bfloat16_as_ushort(lb) << 16);
}

__device__ __forceinline__ void ldm4(uint32_t addr, uint32_t& d0, uint32_t& d1,
                                     uint32_t& d2, uint32_t& d3) {
    asm volatile("ldmatrix.sync.aligned.m8n8.x4.shared.b16 {%0,%1,%2,%3}, [%4];"
                 : "=r"(d0), "=r"(d1), "=r"(d2), "=r"(d3) : "r"(addr));
}

__device__ __forceinline__ void mma16816(float* c, const uint32_t* a,
                                         const uint32_t* b) {
    asm volatile(
        "mma.sync.aligned.m16n8k16.row.col.f32.bf16.bf16.f32 "
        "{%0,%1,%2,%3}, {%4,%5,%6,%7}, {%8,%9}, {%0,%1,%2,%3};"
        : "+f"(c[0]), "+f"(c[1]), "+f"(c[2]), "+f"(c[3])
        : "r"(a[0]), "r"(a[1]), "r"(a[2]), "r"(a[3]), "r"(b[0]), "r"(b[1]));
}

__device__ __forceinline__ void cp16(uint32_t saddr, const void* g, bool pred) {
    int sz = pred ? 16 : 0;
    asm volatile("cp.async.cg.shared.global [%0], [%1], 16, %2;"
                 :: "r"(saddr), "l"(g), "r"(sz));
}
#define CP_COMMIT() asm volatile("cp.async.commit_group;" ::: "memory")
#define CP_WAIT0()  asm volatile("cp.async.wait_group 0;" ::: "memory")
#define CP_WAIT1()  asm volatile("cp.async.wait_group 1;" ::: "memory")

// One K=128 GEMM pass over an M-row tile; warp tile 32x32 at (wm, wn).
__device__ __forceinline__ void gemm_pass(uint32_t sA, uint32_t sW,
                                          float acc[2][4][4],
                                          int wm, int wn, int lane) {
#pragma unroll
    for (int ks = 0; ks < 8; ks++) {
        const int kc = ks * 2;
        uint32_t a[2][4];
#pragma unroll
        for (int s = 0; s < 2; s++) {
            int row = wm * 32 + s * 16 + (lane & 7) + ((lane >> 3) & 1) * 8;
            int chunk = ((kc + (lane >> 4)) ^ (row & 7)) & 15;
            ldm4(sA + row * 256 + chunk * 16, a[s][0], a[s][1], a[s][2], a[s][3]);
        }
        uint32_t b[4][2];
#pragma unroll
        for (int p = 0; p < 2; p++) {
            int row = wn * 32 + p * 16 + (lane & 7) + (lane >> 4) * 8;
            int chunk = ((kc + ((lane >> 3) & 1)) ^ (row & 7)) & 15;
            ldm4(sW + row * 256 + chunk * 16,
                 b[2 * p][0], b[2 * p][1], b[2 * p + 1][0], b[2 * p + 1][1]);
        }
#pragma unroll
        for (int s = 0; s < 2; s++)
#pragma unroll
            for (int nt = 0; nt < 4; nt++)
                mma16816(acc[s][nt], a[s], b[nt]);
    }
}

__device__ __forceinline__ void zero_acc(float acc[2][4][4]) {
#pragma unroll
    for (int s = 0; s < 2; s++)
#pragma unroll
        for (int nt = 0; nt < 4; nt++)
#pragma unroll
            for (int j = 0; j < 4; j++) acc[s][nt][j] = 0.f;
}

// gmem fp32 tile -> split -> swizzled A hi/lo bf16 tiles (M=128, 512 thr)
__device__ __forceinline__ void load_split128(const float* __restrict__ X,
                                              char* sm, uint32_t ahi, uint32_t alo,
                                              int row0, int N, int tid) {
#pragma unroll
    for (int i = tid; i < 4096; i += NT2) {
        int r = i >> 5, c4 = i & 31, g = row0 + r;
        float4 x = make_float4(0.f, 0.f, 0.f, 0.f);
        if (g < N) x = *reinterpret_cast<const float4*>(X + (size_t)g * D + c4 * 4);
        uint32_t h0, l0, h1, l1;
        split2(x.x, x.y, h0, l0);
        split2(x.z, x.w, h1, l1);
        uint32_t off = swz(r, c4 * 4);
        *reinterpret_cast<uint2*>(sm + ahi + off) = make_uint2(h0, h1);
        *reinterpret_cast<uint2*>(sm + alo + off) = make_uint2(l0, l1);
    }
}

// --------------------------- mlp2 persistent -------------------------------
// smem: [W0h W0l W1h W1l 128KB][Ahi 32KB][Alo 32KB][bias 1KB]
#define MS_W    0
#define MS_AHI  131072
#define MS_ALO  163840
#define MS_B    196608
#define MS_TOT  197632

extern "C" __global__ void __launch_bounds__(NT2, 1)
mlp2_mma_kernel(const float* __restrict__ X, const uint4* __restrict__ Wimg,
                const float* __restrict__ bias, float* __restrict__ Y, int N) {
    extern __shared__ char sm[];
    const uint32_t sb = smem_u32(sm);
    const int tid = threadIdx.x, wid = tid >> 5, lane = tid & 31;
    const int wm = wid >> 2, wn = wid & 3;
    const int tiles = (N + 127) / 128;
    const int G = gridDim.x;
    float* bs = reinterpret_cast<float*>(sm + MS_B);

#pragma unroll 4
    for (int i = tid; i < 8192; i += NT2)     // 128KB resident weights
        cp16(sb + MS_W + i * 16, Wimg + i, true);
    if (tid < 2 * D) bs[tid] = bias[tid];
    CP_COMMIT();
    CP_WAIT0();
    __syncthreads();

    for (int t = blockIdx.x; t < tiles; t += G) {
        const int row0 = t * 128;
        load_split128(X, sm, MS_AHI, MS_ALO, row0, N, tid);
        __syncthreads();

        float acc[2][4][4];
        zero_acc(acc);
        gemm_pass(sb + MS_AHI, sb + MS_W,         acc, wm, wn, lane);
        gemm_pass(sb + MS_ALO, sb + MS_W,         acc, wm, wn, lane);
        gemm_pass(sb + MS_AHI, sb + MS_W + 32768, acc, wm, wn, lane);
        __syncthreads();

        // epilogue 1: bias + relu, split hidden back into A tiles
#pragma unroll
        for (int s = 0; s < 2; s++) {
#pragma unroll
            for (int nt = 0; nt < 4; nt++) {
                int m = wm * 32 + s * 16 + (lane >> 2);
                int n = wn * 32 + nt * 8 + (lane & 3) * 2;
                float b0 = bs[n], b1 = bs[n + 1];
                uint32_t h, l;
                float v0 = fmaxf(acc[s][nt][0] + b0, 0.f);
                float v1 = fmaxf(acc[s][nt][1] + b1, 0.f);
                split2(v0, v1, h, l);
                uint32_t off = swz(m, n);
                *reinterpret_cast<uint32_t*>(sm + MS_AHI + off) = h;
                *reinterpret_cast<uint32_t*>(sm + MS_ALO + off) = l;
                v0 = fmaxf(acc[s][nt][2] + b0, 0.f);
                v1 = fmaxf(acc[s][nt][3] + b1, 0.f);
                split2(v0, v1, h, l);
                off = swz(m + 8, n);
                *reinterpret_cast<uint32_t*>(sm + MS_AHI + off) = h;
                *reinterpret_cast<uint32_t*>(sm + MS_ALO + off) = l;
            }
        }
        __syncthreads();

        zero_acc(acc);
        gemm_pass(sb + MS_AHI, sb + MS_W + 65536, acc, wm, wn, lane);
        gemm_pass(sb + MS_ALO, sb + MS_W + 65536, acc, wm, wn, lane);
        gemm_pass(sb + MS_AHI, sb + MS_W + 98304, acc, wm, wn, lane);

        // epilogue 2: bias + fp32 store
#pragma unroll
        for (int s = 0; s < 2; s++) {
#pragma unroll
            for (int nt = 0; nt < 4; nt++) {
                int m = wm * 32 + s * 16 + (lane >> 2);
                int n = wn * 32 + nt * 8 + (lane & 3) * 2;
                float b0 = bs[D + n], b1 = bs[D + n + 1];
                int g0 = row0 + m, g1 = row0 + m + 8;
                if (g0 < N) {
                    float2 o = make_float2(acc[s][nt][0] + b0, acc[s][nt][1] + b1);
                    *reinterpret_cast<float2*>(Y + (size_t)g0 * D + n) = o;
                }
                if (g1 < N) {
                    float2 o = make_float2(acc[s][nt][2] + b0, acc[s][nt][3] + b1);
                    *reinterpret_cast<float2*>(Y + (size_t)g1 * D + n) = o;
                }
            }
        }
        __syncthreads();
    }
}

// --------------------------- update persistent -----------------------------
// smem: [Wh x3 96KB][Wl stream 2x32KB][Ahi 32KB][Alo 32KB][bias 512B]
#define US_WH   0
#define US_WL   98304
#define US_AHI  163840
#define US_ALO  196608
#define US_B    229376
#define US_TOT  229888

extern "C" __global__ void __launch_bounds__(NT2, 1)
update_mma_kernel(const float* __restrict__ X0, const float* __restrict__ X1,
                  const float* __restrict__ X2, const uint4* __restrict__ Wimg,
                  const float* __restrict__ bias, float* __restrict__ Y, int N) {
    extern __shared__ char sm[];
    const uint32_t sb = smem_u32(sm);
    const int tid = threadIdx.x, wid = tid >> 5, lane = tid & 31;
    const int wm = wid >> 2, wn = wid & 3;
    const int tiles = (N + 127) / 128;
    const int G = gridDim.x;
    float* bs = reinterpret_cast<float*>(sm + US_B);

    // resident hi chunks (3 x 32KB); wimg chunk s: hi at uint4 s*4096, lo +2048
#pragma unroll 2
    for (int i = tid; i < 6144; i += NT2) {
        int chunk = i >> 11, off = i & 2047;
        cp16(sb + US_WH + i * 16, Wimg + chunk * 4096 + off, true);
    }
    // initial lo prefetch: chunk 0 -> buffer 0
    for (int i = tid; i < 2048; i += NT2)
        cp16(sb + US_WL + i * 16, Wimg + 2048 + i, true);
    if (tid < D) bs[tid] = bias[tid];
    CP_COMMIT();
    CP_WAIT0();
    __syncthreads();

    const float* srcs[3] = {X0, X1, X2};
    int pb = 0;   // current lo buffer parity

    for (int t = blockIdx.x; t < tiles; t += G) {
        const int row0 = t * 128;
        float acc[2][4][4];
        zero_acc(acc);

#pragma unroll
        for (int s = 0; s < 3; s++) {
            // prefetch next lo chunk into other buffer (wraps to 0 for next tile)
            int nc = (s < 2) ? s + 1 : 0;
            for (int i = tid; i < 2048; i += NT2)
                cp16(sb + US_WL + (pb ^ 1) * 32768 + i * 16,
                     Wimg + nc * 4096 + 2048 + i, true);
            CP_COMMIT();

            load_split128(srcs[s], sm, US_AHI, US_ALO, row0, N, tid);
            __syncthreads();

            gemm_pass(sb + US_AHI, sb + US_WH + s * 32768, acc, wm, wn, lane);
            gemm_pass(sb + US_ALO, sb + US_WH + s * 32768, acc, wm, wn, lane);
            CP_WAIT1();            // current lo buffer (committed last chunk) ready
            __syncthreads();
            gemm_pass(sb + US_AHI, sb + US_WL + pb * 32768, acc, wm, wn, lane);
            __syncthreads();       // A tiles free for next split
            pb ^= 1;
        }

#pragma unroll
        for (int s = 0; s < 2; s++) {
#pragma unroll
            for (int nt = 0; nt < 4; nt++) {
                int m = wm * 32 + s * 16 + (lane >> 2);
                int n = wn * 32 + nt * 8 + (lane & 3) * 2;
                float b0 = bs[n], b1 = bs[n + 1];
                int g0 = row0 + m, g1 = row0 + m + 8;
                if (g0 < N) {
                    float2 o = make_float2(acc[s][nt][0] + b0, acc[s][nt][1] + b1);
                    *reinterpret_cast<float2*>(Y + (size_t)g0 * D + n) = o;
                }
                if (g1 < N) {
                    float2 o = make_float2(acc[s][nt][2] + b0, acc[s][nt][3] + b1);
                    *reinterpret_cast<float2*>(Y + (size_t)g1 * D + n) = o;
                }
            }
        }
    }
}

// ----------------------- weight image conversion ----------------------------
extern "C" __global__ void wconv_mlp_kernel(const float* __restrict__ W,
                                            unsigned char* __restrict__ img) {
    int t = blockIdx.x * blockDim.x + threadIdx.x;
    if (t >= 2 * 128 * 128) return;
    int l = t >> 14, k = (t >> 7) & 127, n = t & 127;
    float w = W[t];
    __nv_bfloat16 h = __float2bfloat16(w);
    __nv_bfloat16 lo = __float2bfloat16(w - __bfloat162float(h));
    unsigned char* base = img + (size_t)l * 65536;
    uint32_t off = swz(n, k);
    *reinterpret_cast<__nv_bfloat16*>(base + off) = h;
    *reinterpret_cast<__nv_bfloat16*>(base + 32768 + off) = lo;
}

extern "C" __global__ void wconv_upd_kernel(const float* __restrict__ W,
                                            unsigned char* __restrict__ img) {
    int t = blockIdx.x * blockDim.x + threadIdx.x;
    if (t >= 384 * 128) return;
    int k = t >> 7, n = t & 127;
    int s = k >> 7, kl = k & 127;
    float w = W[t];
    __nv_bfloat16 h = __float2bfloat16(w);
    __nv_bfloat16 lo = __float2bfloat16(w - __bfloat162float(h));
    unsigned char* base = img + (size_t)s * 65536;
    uint32_t off = swz(n, kl);
    *reinterpret_cast<__nv_bfloat16*>(base + off) = h;
    *reinterpret_cast<__nv_bfloat16*>(base + 32768 + off) = lo;
}

// ------------------------------ CSR build -----------------------------------
extern "C" __global__ void degree_kernel(const int* __restrict__ vE,
                                         const int* __restrict__ cE,
                                         const int* __restrict__ pE,
                                         const int* __restrict__ nE, int Eh) {
    int t = blockIdx.x * blockDim.x + threadIdx.x;
    if (t < Eh) {
        int e = pE[t];
        atomicAdd(&g_degi_pv[vE[e]], 1);
        atomicAdd(&g_degi_pc[cE[e]], 1);
    } else if (t < 2 * Eh) {
        int e = nE[t - Eh];
        atomicAdd(&g_degi_nv[vE[e]], 1);
        atomicAdd(&g_degi_nc[cE[e]], 1);
    }
}

extern "C" __global__ void __launch_bounds__(1024)
scan4_kernel(int V, int C) {
    const int* d; int* r; int n;
    switch (blockIdx.x) {
        case 0:  d = g_degi_pc; r = g_rp_pc; n = C; break;
        case 1:  d = g_degi_nc; r = g_rp_nc; n = C; break;
        case 2:  d = g_degi_pv; r = g_rp_pv; n = V; break;
        default: d = g_degi_nv; r = g_rp_nv; n = V; break;
    }
    __shared__ int wsum[32];
    __shared__ int sh_carry, sh_total;
    int tid = threadIdx.x, lane = tid & 31, wid = tid >> 5;
    if (tid == 0) sh_carry = 0;
    __syncthreads();
    for (int base = 0; base < n; base += 1024) {
        int i = base + tid;
        int v = (i < n) ? d[i] : 0;
        int incl = v;
#pragma unroll
        for (int o = 1; o < 32; o <<= 1) {
            int x = __shfl_up_sync(0xffffffffu, incl, o);
            if (lane >= o) incl += x;
        }
        if (lane == 31) wsum[wid] = incl;
        __syncthreads();
        if (tid < 32) {
            int s = wsum[tid], ip = s;
#pragma unroll
            for (int o = 1; o < 32; o <<= 1) {
                int x = __shfl_up_sync(0xffffffffu, ip, o);
                if (tid >= o) ip += x;
            }
            wsum[tid] = ip - s;
            if (tid == 31) sh_total = ip;
        }
        __syncthreads();
        if (i < n) r[i] = sh_carry + wsum[wid] + incl - v;
        __syncthreads();
        if (tid == 0) sh_carry += sh_total;
        __syncthreads();
    }
    if (tid == 0) r[n] = sh_carry;
}

extern "C" __global__ void fill_kernel(const int* __restrict__ vE,
                                       const int* __restrict__ cE,
                                       const int* __restrict__ pE,
                                       const int* __restrict__ nE, int Eh) {
    int t = blockIdx.x * blockDim.x + threadIdx.x;
    if (t < Eh) {
        int e = pE[t];
        int v = vE[e], c = cE[e];
        float inv = rsqrtf((float)max(g_degi_pv[v], 1) * (float)max(g_degi_pc[c], 1));
        int pos = g_rp_pc[c] + atomicAdd(&g_fl_pc[c], 1);
        g_sl_pc_src[pos] = v;
        g_sl_pc_w[pos] = inv;
        int pos2 = g_rp_pv[v] + atomicAdd(&g_fl_pv[v], 1);
        g_sl_pv_src[pos2] = c;
        g_sl_pv_w[pos2] = inv;
    } else if (t < 2 * Eh) {
        int e = nE[t - Eh];
        int v = vE[e], c = cE[e];
        float inv = rsqrtf((float)max(g_degi_nv[v], 1) * (float)max(g_degi_nc[c], 1));
        int pos = g_rp_nc[c] + atomicAdd(&g_fl_nc[c], 1);
        g_sl_nc_src[pos] = v;
        g_sl_nc_w[pos] = inv;
        int pos2 = g_rp_nv[v] + atomicAdd(&g_fl_nv[v], 1);
        g_sl_nv_src[pos2] = c;
        g_sl_nv_w[pos2] = inv;
    }
}

// ------------------------------ CSR gather ----------------------------------
extern "C" __global__ void __launch_bounds__(NT)
gather_kernel(const float* __restrict__ src_mat, float* __restrict__ dst,
              const int* __restrict__ rp, const int* __restrict__ sl_src,
              const float* __restrict__ sl_w, int n) {
    long t = (long)blockIdx.x * blockDim.x + threadIdx.x;
    int node = (int)(t >> 5), lane = (int)(t & 31);
    if (node >= n) return;
    int j = rp[node], end = rp[node + 1];
    float4 acc = make_float4(0.f, 0.f, 0.f, 0.f);
    int s_next = 0; float w_next = 0.f;
    if (j < end) { s_next = __ldg(sl_src + j); w_next = __ldg(sl_w + j); }
    while (j < end) {
        int s = s_next; float w = w_next;
        j++;
        if (j < end) { s_next = __ldg(sl_src + j); w_next = __ldg(sl_w + j); }
        float4 x = __ldg(reinterpret_cast<const float4*>(src_mat + (size_t)s * D) + lane);
        acc.x = fmaf(w, x.x, acc.x);
        acc.y = fmaf(w, x.y, acc.y);
        acc.z = fmaf(w, x.z, acc.z);
        acc.w = fmaf(w, x.w, acc.w);
    }
    reinterpret_cast<float4*>(dst + (size_t)node * D)[lane] = acc;
}

// -------------------------------- launch ------------------------------------
extern "C" void kernel_launch(void* const* d_in, const int* in_sizes, int n_in,
                              void* d_out, int out_size) {
    int base = (n_in >= 20) ? 2 : 0;
    const int*   v_edge = (const int*)d_in[base + 0];
    const int*   c_edge = (const int*)d_in[base + 1];
    const int*   p_edge = (const int*)d_in[base + 2];
    const int*   n_edge = (const int*)d_in[base + 3];
    const float* v0     = (const float*)d_in[base + 4];
    const float* c0     = (const float*)d_in[base + 5];
    const float *Wm[4], *Bm[4];
    for (int i = 0; i < 4; i++) {
        Wm[i] = (const float*)d_in[base + 6 + 2 * i];
        Bm[i] = (const float*)d_in[base + 7 + 2 * i];
    }
    const float* cuW = (const float*)d_in[base + 14];
    const float* cub = (const float*)d_in[base + 15];
    const float* vuW = (const float*)d_in[base + 16];
    const float* vub = (const float*)d_in[base + 17];

    const int Eh = in_sizes[base + 2];
    const int V  = in_sizes[base + 4] / D;
    const int C  = in_sizes[base + 5] / D;

    void* p;
    float *t_pv2c, *t_nv2c, *t_pc2v, *t_nc2v, *agg_c, *agg_v;
    int *degi_pv, *degi_nv, *degi_pc, *degi_nc;
    int *rp_pc, *rp_nc, *rp_pv, *rp_nv;
    int *fl_pc, *fl_nc, *fl_pv, *fl_nv;
    int *sl_pc_s, *sl_nc_s, *sl_pv_s, *sl_nv_s;
    float *sl_pc_w, *sl_nc_w, *sl_pv_w, *sl_nv_w;
    unsigned char *img_mlp, *img_cu, *img_vu;
    cudaGetSymbolAddress(&p, g_t_pv2c); t_pv2c = (float*)p;
    cudaGetSymbolAddress(&p, g_t_nv2c); t_nv2c = (float*)p;
    cudaGetSymbolAddress(&p, g_t_pc2v); t_pc2v = (float*)p;
    cudaGetSymbolAddress(&p, g_t_nc2v); t_nc2v = (float*)p;
    cudaGetSymbolAddress(&p, g_agg_c);  agg_c  = (float*)p;
    cudaGetSymbolAddress(&p, g_agg_v);  agg_v  = (float*)p;
    cudaGetSymbolAddress(&p, g_degi_pv); degi_pv = (int*)p;
    cudaGetSymbolAddress(&p, g_degi_nv); degi_nv = (int*)p;
    cudaGetSymbolAddress(&p, g_degi_pc); degi_pc = (int*)p;
    cudaGetSymbolAddress(&p, g_degi_nc); degi_nc = (int*)p;
    cudaGetSymbolAddress(&p, g_rp_pc); rp_pc = (int*)p;
    cudaGetSymbolAddress(&p, g_rp_nc); rp_nc = (int*)p;
    cudaGetSymbolAddress(&p, g_rp_pv); rp_pv = (int*)p;
    cudaGetSymbolAddress(&p, g_rp_nv); rp_nv = (int*)p;
    cudaGetSymbolAddress(&p, g_fl_pc); fl_pc = (int*)p;
    cudaGetSymbolAddress(&p, g_fl_nc); fl_nc = (int*)p;
    cudaGetSymbolAddress(&p, g_fl_pv); fl_pv = (int*)p;
    cudaGetSymbolAddress(&p, g_fl_nv); fl_nv = (int*)p;
    cudaGetSymbolAddress(&p, g_sl_pc_src); sl_pc_s = (int*)p;
    cudaGetSymbolAddress(&p, g_sl_nc_src); sl_nc_s = (int*)p;
    cudaGetSymbolAddress(&p, g_sl_pv_src); sl_pv_s = (int*)p;
    cudaGetSymbolAddress(&p, g_sl_nv_src); sl_nv_s = (int*)p;
    cudaGetSymbolAddress(&p, g_sl_pc_w); sl_pc_w = (float*)p;
    cudaGetSymbolAddress(&p, g_sl_nc_w); sl_nc_w = (float*)p;
    cudaGetSymbolAddress(&p, g_sl_pv_w); sl_pv_w = (float*)p;
    cudaGetSymbolAddress(&p, g_sl_nv_w); sl_nv_w = (float*)p;
    cudaGetSymbolAddress(&p, g_wimg_mlp); img_mlp = (unsigned char*)p;
    cudaGetSymbolAddress(&p, g_wimg_cu);  img_cu  = (unsigned char*)p;
    cudaGetSymbolAddress(&p, g_wimg_vu);  img_vu  = (unsigned char*)p;

    float* agg_c_p = agg_c;
    float* agg_c_n = agg_c + (size_t)CMAX * D;
    float* agg_v_p = agg_v;
    float* agg_v_n = agg_v + (size_t)VMAX * D;

    float* outv = (float*)d_out;
    float* outc = outv + (size_t)4 * V * D;

    int sms = 148;
    cudaDeviceGetAttribute(&sms, cudaDevAttrMultiProcessorCount, 0);

    cudaFuncSetAttribute(mlp2_mma_kernel,
                         cudaFuncAttributeMaxDynamicSharedMemorySize, MS_TOT);
    cudaFuncSetAttribute(update_mma_kernel,
                         cudaFuncAttributeMaxDynamicSharedMemorySize, US_TOT);

    // ---- prep: degrees -> scan -> CSR fill; weight images ----
    cudaMemsetAsync(degi_pv, 0, (size_t)V * sizeof(int));
    cudaMemsetAsync(degi_nv, 0, (size_t)V * sizeof(int));
    cudaMemsetAsync(degi_pc, 0, (size_t)C * sizeof(int));
    cudaMemsetAsync(degi_nc, 0, (size_t)C * sizeof(int));
    cudaMemsetAsync(fl_pc, 0, (size_t)C * sizeof(int));
    cudaMemsetAsync(fl_nc, 0, (size_t)C * sizeof(int));
    cudaMemsetAsync(fl_pv, 0, (size_t)V * sizeof(int));
    cudaMemsetAsync(fl_nv, 0, (size_t)V * sizeof(int));
    {
        int blk = (2 * Eh + NT - 1) / NT;
        degree_kernel<<<blk, NT>>>(v_edge, c_edge, p_edge, n_edge, Eh);
        scan4_kernel<<<4, 1024>>>(V, C);
        fill_kernel<<<blk, NT>>>(v_edge, c_edge, p_edge, n_edge, Eh);
    }
    for (int i = 0; i < 4; i++)
        wconv_mlp_kernel<<<128, 256>>>(Wm[i], img_mlp + (size_t)i * 2 * 65536);
    wconv_upd_kernel<<<192, 256>>>(cuW, img_cu);
    wconv_upd_kernel<<<192, 256>>>(vuW, img_vu);

    cudaMemcpyAsync(outv, v0, (size_t)V * D * sizeof(float), cudaMemcpyDeviceToDevice);
    cudaMemcpyAsync(outc, c0, (size_t)C * D * sizeof(float), cudaMemcpyDeviceToDevice);

    const int gthC = (int)(((long)C * 32 + NT - 1) / NT);
    const int gthV = (int)(((long)V * 32 + NT - 1) / NT);

    for (int t = 0; t < 3; t++) {
        const float* vin = outv + (size_t)t * V * D;
        const float* cin = outc + (size_t)t * C * D;
        float* vout = outv + (size_t)(t + 1) * V * D;
        float* cout = outc + (size_t)(t + 1) * C * D;

        mlp2_mma_kernel<<<sms, NT2, MS_TOT>>>(
            vin, (const uint4*)(img_mlp + 0 * 2 * 65536), Bm[0], t_pv2c, V);
        mlp2_mma_kernel<<<sms, NT2, MS_TOT>>>(
            vin, (const uint4*)(img_mlp + 1 * 2 * 65536), Bm[1], t_nv2c, V);
        mlp2_mma_kernel<<<sms, NT2, MS_TOT>>>(
            cin, (const uint4*)(img_mlp + 2 * 2 * 65536), Bm[2], t_pc2v, C);
        mlp2_mma_kernel<<<sms, NT2, MS_TOT>>>(
            cin, (const uint4*)(img_mlp + 3 * 2 * 65536), Bm[3], t_nc2v, C);

        gather_kernel<<<gthC, NT>>>(t_pv2c, agg_c_p, rp_pc, sl_pc_s, sl_pc_w, C);
        gather_kernel<<<gthC, NT>>>(t_nv2c, agg_c_n, rp_nc, sl_nc_s, sl_nc_w, C);
        gather_kernel<<<gthV, NT>>>(t_pc2v, agg_v_p, rp_pv, sl_pv_s, sl_pv_w, V);
        gather_kernel<<<gthV, NT>>>(t_nc2v, agg_v_n, rp_nv, sl_nv_s, sl_nv_w, V);

        update_mma_kernel<<<sms, NT2, US_TOT>>>(
            cin, agg_c_p, agg_c_n, (const uint4*)img_cu, cub, cout, C);
        update_mma_kernel<<<sms, NT2, US_TOT>>>(
            vin, agg_v_p, agg_v_n, (const uint4*)img_vu, vub, vout, V);
    }
}

// round 6
// speedup vs baseline: 2.5079x; 2.5079x over previous
#include <cuda_runtime.h>
#include <cuda_fp16.h>
#include <cstdint>

// ---------------------------------------------------------------------------
// GCN_VCG, round 6 (revert to R4 skeleton + fp16 2-pass):
//  - GEMMs: persistent CTAs, M=64 tiles, 8 warps (2m x 4n, warp tile 32x32),
//    fp16 mma.sync 2-pass split:  A@B = Ah@Bh + Al@Bh  (== A @ fp16(B)),
//    weights fp16-hi resident in smem (mlp: 64KB -> 2 CTAs/SM).
//  - Aggregation: CSR gather (warp per dst node), no atomics.
// ---------------------------------------------------------------------------

#define D        128
#define NT       256
#define VMAX     50000
#define CMAX     210000
#define EHMAX    315000

// ------------------------- scratch (no runtime alloc) ----------------------
__device__ float g_t_pv2c[(size_t)VMAX * D];
__device__ float g_t_nv2c[(size_t)VMAX * D];
__device__ float g_t_pc2v[(size_t)CMAX * D];
__device__ float g_t_nc2v[(size_t)CMAX * D];
__device__ float g_agg_c[2][(size_t)CMAX * D];
__device__ float g_agg_v[2][(size_t)VMAX * D];
// weight images (fp16 hi only, swizzled): mlp = 2 layers x 32KB; upd = 3 x 32KB
__device__ unsigned char g_wimg_mlp[4][2 * 32768];
__device__ unsigned char g_wimg_cu[3 * 32768];
__device__ unsigned char g_wimg_vu[3 * 32768];
// CSR structures (iteration-invariant)
__device__ int   g_degi_pv[VMAX], g_degi_nv[VMAX];
__device__ int   g_degi_pc[CMAX], g_degi_nc[CMAX];
__device__ int   g_rp_pc[CMAX + 1], g_rp_nc[CMAX + 1];
__device__ int   g_rp_pv[VMAX + 1], g_rp_nv[VMAX + 1];
__device__ int   g_fl_pc[CMAX], g_fl_nc[CMAX], g_fl_pv[VMAX], g_fl_nv[VMAX];
__device__ int   g_sl_pc_src[EHMAX], g_sl_nc_src[EHMAX];
__device__ int   g_sl_pv_src[EHMAX], g_sl_nv_src[EHMAX];
__device__ float g_sl_pc_w[EHMAX], g_sl_nc_w[EHMAX];
__device__ float g_sl_pv_w[EHMAX], g_sl_nv_w[EHMAX];

// ------------------------------ helpers ------------------------------------
__device__ __forceinline__ uint32_t smem_u32(const void* p) {
    uint32_t a;
    asm("{ .reg .u64 t; cvta.to.shared.u64 t, %1; cvt.u32.u64 %0, t; }"
        : "=r"(a) : "l"(p));
    return a;
}

// byte offset of fp16 (row r, col c) in a [rows x 128] b16 tile; 256B rows,
// 16B chunks XOR-swizzled by (r&7) for conflict-free ldmatrix.
__device__ __host__ __forceinline__ uint32_t swz(int r, int c) {
    return ((uint32_t)r << 8) + ((uint32_t)(((c >> 3) ^ (r & 7)) & 15) << 4)
         + ((uint32_t)(c & 7) << 1);
}

// fp16 two-term split of a pair of floats
__device__ __forceinline__ void split2(float a, float b, uint32_t& hi, uint32_t& lo) {
    __half ha = __float2half_rn(a);
    __half hb = __float2half_rn(b);
    __half la = __float2half_rn(a - __half2float(ha));
    __half lb = __float2half_rn(b - __half2float(hb));
    hi = (uint32_t)__half_as_ushort(ha) | ((uint32_t)__half_as_ushort(hb) << 16);
    lo = (uint32_t)__half_as_ushort(la) | ((uint32_t)__half_as_ushort(lb) << 16);
}

__device__ __forceinline__ void ldm4(uint32_t addr, uint32_t& d0, uint32_t& d1,
                                     uint32_t& d2, uint32_t& d3) {
    asm volatile("ldmatrix.sync.aligned.m8n8.x4.shared.b16 {%0,%1,%2,%3}, [%4];"
                 : "=r"(d0), "=r"(d1), "=r"(d2), "=r"(d3) : "r"(addr));
}

__device__ __forceinline__ void mma16816(float* c, const uint32_t* a,
                                         const uint32_t* b) {
    asm volatile(
        "mma.sync.aligned.m16n8k16.row.col.f32.f16.f16.f32 "
        "{%0,%1,%2,%3}, {%4,%5,%6,%7}, {%8,%9}, {%0,%1,%2,%3};"
        : "+f"(c[0]), "+f"(c[1]), "+f"(c[2]), "+f"(c[3])
        : "r"(a[0]), "r"(a[1]), "r"(a[2]), "r"(a[3]), "r"(b[0]), "r"(b[1]));
}

__device__ __forceinline__ void cp16(uint32_t saddr, const void* g, bool pred) {
    int sz = pred ? 16 : 0;
    asm volatile("cp.async.cg.shared.global [%0], [%1], 16, %2;"
                 :: "r"(saddr), "l"(g), "r"(sz));
}
#define CP_COMMIT() asm volatile("cp.async.commit_group;" ::: "memory")
#define CP_WAIT0()  asm volatile("cp.async.wait_group 0;" ::: "memory")

// One K=128 GEMM pass: M=64 tile, 8 warps as 2m x 4n, warp tile 32x32.
__device__ __forceinline__ void gemm_pass64(uint32_t sA, uint32_t sW,
                                            float acc[2][4][4],
                                            int wm, int wn, int lane) {
#pragma unroll
    for (int ks = 0; ks < 8; ks++) {
        const int kc = ks * 2;
        uint32_t a[2][4];
#pragma unroll
        for (int s = 0; s < 2; s++) {
            int row = wm * 32 + s * 16 + (lane & 7) + ((lane >> 3) & 1) * 8;
            int chunk = ((kc + (lane >> 4)) ^ (row & 7)) & 15;
            ldm4(sA + row * 256 + chunk * 16, a[s][0], a[s][1], a[s][2], a[s][3]);
        }
        uint32_t b[4][2];
#pragma unroll
        for (int p = 0; p < 2; p++) {
            int row = wn * 32 + p * 16 + (lane & 7) + (lane >> 4) * 8;
            int chunk = ((kc + ((lane >> 3) & 1)) ^ (row & 7)) & 15;
            ldm4(sW + row * 256 + chunk * 16,
                 b[2 * p][0], b[2 * p][1], b[2 * p + 1][0], b[2 * p + 1][1]);
        }
#pragma unroll
        for (int s = 0; s < 2; s++)
#pragma unroll
            for (int nt = 0; nt < 4; nt++)
                mma16816(acc[s][nt], a[s], b[nt]);
    }
}

__device__ __forceinline__ void zero_acc(float acc[2][4][4]) {
#pragma unroll
    for (int s = 0; s < 2; s++)
#pragma unroll
        for (int nt = 0; nt < 4; nt++)
#pragma unroll
            for (int j = 0; j < 4; j++) acc[s][nt][j] = 0.f;
}

// gmem fp32 64-row tile -> fp16 hi/lo swizzled A tiles
__device__ __forceinline__ void load_split64(const float* __restrict__ X,
                                             char* sm, uint32_t ahi, uint32_t alo,
                                             int row0, int N, int tid) {
#pragma unroll
    for (int i = tid; i < 2048; i += NT) {
        int r = i >> 5, c4 = i & 31, g = row0 + r;
        float4 x = make_float4(0.f, 0.f, 0.f, 0.f);
        if (g < N) x = *reinterpret_cast<const float4*>(X + (size_t)g * D + c4 * 4);
        uint32_t h0, l0, h1, l1;
        split2(x.x, x.y, h0, l0);
        split2(x.z, x.w, h1, l1);
        uint32_t off = swz(r, c4 * 4);
        *reinterpret_cast<uint2*>(sm + ahi + off) = make_uint2(h0, h1);
        *reinterpret_cast<uint2*>(sm + alo + off) = make_uint2(l0, l1);
    }
}

// --------------------------- mlp2 persistent -------------------------------
// smem: [W0h 32KB][W1h 32KB][Ahi 16KB][Alo 16KB][bias 1KB] = 99328 B
#define MS_W    0
#define MS_AHI  65536
#define MS_ALO  81920
#define MS_B    98304
#define MS_TOT  99328

extern "C" __global__ void __launch_bounds__(NT, 2)
mlp2_mma_kernel(const float* __restrict__ X, const uint4* __restrict__ Wimg,
                const float* __restrict__ bias, float* __restrict__ Y, int N) {
    extern __shared__ char sm[];
    const uint32_t sb = smem_u32(sm);
    const int tid = threadIdx.x, wid = tid >> 5, lane = tid & 31;
    const int wm = wid >> 2, wn = wid & 3;
    const int tiles = (N + 63) / 64;
    const int G = gridDim.x;
    float* bs = reinterpret_cast<float*>(sm + MS_B);

#pragma unroll 4
    for (int i = tid; i < 4096; i += NT)      // 64KB resident hi weights
        cp16(sb + MS_W + i * 16, Wimg + i, true);
    if (tid < 2 * D) bs[tid] = bias[tid];
    CP_COMMIT();
    CP_WAIT0();
    __syncthreads();

    for (int t = blockIdx.x; t < tiles; t += G) {
        const int row0 = t * 64;
        load_split64(X, sm, MS_AHI, MS_ALO, row0, N, tid);
        __syncthreads();

        float acc[2][4][4];
        zero_acc(acc);
        gemm_pass64(sb + MS_AHI, sb + MS_W, acc, wm, wn, lane);
        gemm_pass64(sb + MS_ALO, sb + MS_W, acc, wm, wn, lane);
        __syncthreads();

        // epilogue 1: bias + relu, split hidden back into A tiles
#pragma unroll
        for (int s = 0; s < 2; s++) {
#pragma unroll
            for (int nt = 0; nt < 4; nt++) {
                int m = wm * 32 + s * 16 + (lane >> 2);
                int n = wn * 32 + nt * 8 + (lane & 3) * 2;
                float b0 = bs[n], b1 = bs[n + 1];
                uint32_t h, l;
                float v0 = fmaxf(acc[s][nt][0] + b0, 0.f);
                float v1 = fmaxf(acc[s][nt][1] + b1, 0.f);
                split2(v0, v1, h, l);
                uint32_t off = swz(m, n);
                *reinterpret_cast<uint32_t*>(sm + MS_AHI + off) = h;
                *reinterpret_cast<uint32_t*>(sm + MS_ALO + off) = l;
                v0 = fmaxf(acc[s][nt][2] + b0, 0.f);
                v1 = fmaxf(acc[s][nt][3] + b1, 0.f);
                split2(v0, v1, h, l);
                off = swz(m + 8, n);
                *reinterpret_cast<uint32_t*>(sm + MS_AHI + off) = h;
                *reinterpret_cast<uint32_t*>(sm + MS_ALO + off) = l;
            }
        }
        __syncthreads();

        zero_acc(acc);
        gemm_pass64(sb + MS_AHI, sb + MS_W + 32768, acc, wm, wn, lane);
        gemm_pass64(sb + MS_ALO, sb + MS_W + 32768, acc, wm, wn, lane);

        // epilogue 2: bias + fp32 store
#pragma unroll
        for (int s = 0; s < 2; s++) {
#pragma unroll
            for (int nt = 0; nt < 4; nt++) {
                int m = wm * 32 + s * 16 + (lane >> 2);
                int n = wn * 32 + nt * 8 + (lane & 3) * 2;
                float b0 = bs[D + n], b1 = bs[D + n + 1];
                int g0 = row0 + m, g1 = row0 + m + 8;
                if (g0 < N) {
                    float2 o = make_float2(acc[s][nt][0] + b0, acc[s][nt][1] + b1);
                    *reinterpret_cast<float2*>(Y + (size_t)g0 * D + n) = o;
                }
                if (g1 < N) {
                    float2 o = make_float2(acc[s][nt][2] + b0, acc[s][nt][3] + b1);
                    *reinterpret_cast<float2*>(Y + (size_t)g1 * D + n) = o;
                }
            }
        }
        __syncthreads();
    }
}

// --------------------------- update persistent -----------------------------
// smem: [Wh x3 96KB][Ahi 16KB][Alo 16KB][bias 512B] = 131584 B
#define US_W    0
#define US_AHI  98304
#define US_ALO  114688
#define US_B    131072
#define US_TOT  131584

extern "C" __global__ void __launch_bounds__(NT, 1)
update_mma_kernel(const float* __restrict__ X0, const float* __restrict__ X1,
                  const float* __restrict__ X2, const uint4* __restrict__ Wimg,
                  const float* __restrict__ bias, float* __restrict__ Y, int N) {
    extern __shared__ char sm[];
    const uint32_t sb = smem_u32(sm);
    const int tid = threadIdx.x, wid = tid >> 5, lane = tid & 31;
    const int wm = wid >> 2, wn = wid & 3;
    const int tiles = (N + 63) / 64;
    const int G = gridDim.x;
    float* bs = reinterpret_cast<float*>(sm + US_B);

#pragma unroll 4
    for (int i = tid; i < 6144; i += NT)      // 96KB resident hi weights
        cp16(sb + US_W + i * 16, Wimg + i, true);
    if (tid < D) bs[tid] = bias[tid];
    CP_COMMIT();
    CP_WAIT0();
    __syncthreads();

    const float* srcs[3] = {X0, X1, X2};

    for (int t = blockIdx.x; t < tiles; t += G) {
        const int row0 = t * 64;
        float acc[2][4][4];
        zero_acc(acc);

#pragma unroll
        for (int s = 0; s < 3; s++) {
            load_split64(srcs[s], sm, US_AHI, US_ALO, row0, N, tid);
            __syncthreads();
            gemm_pass64(sb + US_AHI, sb + US_W + s * 32768, acc, wm, wn, lane);
            gemm_pass64(sb + US_ALO, sb + US_W + s * 32768, acc, wm, wn, lane);
            __syncthreads();
        }

#pragma unroll
        for (int s = 0; s < 2; s++) {
#pragma unroll
            for (int nt = 0; nt < 4; nt++) {
                int m = wm * 32 + s * 16 + (lane >> 2);
                int n = wn * 32 + nt * 8 + (lane & 3) * 2;
                float b0 = bs[n], b1 = bs[n + 1];
                int g0 = row0 + m, g1 = row0 + m + 8;
                if (g0 < N) {
                    float2 o = make_float2(acc[s][nt][0] + b0, acc[s][nt][1] + b1);
                    *reinterpret_cast<float2*>(Y + (size_t)g0 * D + n) = o;
                }
                if (g1 < N) {
                    float2 o = make_float2(acc[s][nt][2] + b0, acc[s][nt][3] + b1);
                    *reinterpret_cast<float2*>(Y + (size_t)g1 * D + n) = o;
                }
            }
        }
    }
}

// ----------------------- weight image conversion ----------------------------
// W[l][k][n] (x@W) -> per layer: swizzled [n][k] fp16 hi (32KB)
extern "C" __global__ void wconv_mlp_kernel(const float* __restrict__ W,
                                            unsigned char* __restrict__ img) {
    int t = blockIdx.x * blockDim.x + threadIdx.x;
    if (t >= 2 * 128 * 128) return;
    int l = t >> 14, k = (t >> 7) & 127, n = t & 127;
    __half h = __float2half_rn(W[t]);
    *reinterpret_cast<__half*>(img + (size_t)l * 32768 + swz(n, k)) = h;
}

extern "C" __global__ void wconv_upd_kernel(const float* __restrict__ W,
                                            unsigned char* __restrict__ img) {
    int t = blockIdx.x * blockDim.x + threadIdx.x;
    if (t >= 384 * 128) return;
    int k = t >> 7, n = t & 127;
    int s = k >> 7, kl = k & 127;
    __half h = __float2half_rn(W[t]);
    *reinterpret_cast<__half*>(img + (size_t)s * 32768 + swz(n, kl)) = h;
}

// ------------------------------ CSR build -----------------------------------
extern "C" __global__ void degree_kernel(const int* __restrict__ vE,
                                         const int* __restrict__ cE,
                                         const int* __restrict__ pE,
                                         const int* __restrict__ nE, int Eh) {
    int t = blockIdx.x * blockDim.x + threadIdx.x;
    if (t < Eh) {
        int e = pE[t];
        atomicAdd(&g_degi_pv[vE[e]], 1);
        atomicAdd(&g_degi_pc[cE[e]], 1);
    } else if (t < 2 * Eh) {
        int e = nE[t - Eh];
        atomicAdd(&g_degi_nv[vE[e]], 1);
        atomicAdd(&g_degi_nc[cE[e]], 1);
    }
}

extern "C" __global__ void __launch_bounds__(1024)
scan4_kernel(int V, int C) {
    const int* d; int* r; int n;
    switch (blockIdx.x) {
        case 0:  d = g_degi_pc; r = g_rp_pc; n = C; break;
        case 1:  d = g_degi_nc; r = g_rp_nc; n = C; break;
        case 2:  d = g_degi_pv; r = g_rp_pv; n = V; break;
        default: d = g_degi_nv; r = g_rp_nv; n = V; break;
    }
    __shared__ int wsum[32];
    __shared__ int sh_carry, sh_total;
    int tid = threadIdx.x, lane = tid & 31, wid = tid >> 5;
    if (tid == 0) sh_carry = 0;
    __syncthreads();
    for (int base = 0; base < n; base += 1024) {
        int i = base + tid;
        int v = (i < n) ? d[i] : 0;
        int incl = v;
#pragma unroll
        for (int o = 1; o < 32; o <<= 1) {
            int x = __shfl_up_sync(0xffffffffu, incl, o);
            if (lane >= o) incl += x;
        }
        if (lane == 31) wsum[wid] = incl;
        __syncthreads();
        if (tid < 32) {
            int s = wsum[tid], ip = s;
#pragma unroll
            for (int o = 1; o < 32; o <<= 1) {
                int x = __shfl_up_sync(0xffffffffu, ip, o);
                if (tid >= o) ip += x;
            }
            wsum[tid] = ip - s;
            if (tid == 31) sh_total = ip;
        }
        __syncthreads();
        if (i < n) r[i] = sh_carry + wsum[wid] + incl - v;
        __syncthreads();
        if (tid == 0) sh_carry += sh_total;
        __syncthreads();
    }
    if (tid == 0) r[n] = sh_carry;
}

extern "C" __global__ void fill_kernel(const int* __restrict__ vE,
                                       const int* __restrict__ cE,
                                       const int* __restrict__ pE,
                                       const int* __restrict__ nE, int Eh) {
    int t = blockIdx.x * blockDim.x + threadIdx.x;
    if (t < Eh) {
        int e = pE[t];
        int v = vE[e], c = cE[e];
        float inv = rsqrtf((float)max(g_degi_pv[v], 1) * (float)max(g_degi_pc[c], 1));
        int pos = g_rp_pc[c] + atomicAdd(&g_fl_pc[c], 1);
        g_sl_pc_src[pos] = v;
        g_sl_pc_w[pos] = inv;
        int pos2 = g_rp_pv[v] + atomicAdd(&g_fl_pv[v], 1);
        g_sl_pv_src[pos2] = c;
        g_sl_pv_w[pos2] = inv;
    } else if (t < 2 * Eh) {
        int e = nE[t - Eh];
        int v = vE[e], c = cE[e];
        float inv = rsqrtf((float)max(g_degi_nv[v], 1) * (float)max(g_degi_nc[c], 1));
        int pos = g_rp_nc[c] + atomicAdd(&g_fl_nc[c], 1);
        g_sl_nc_src[pos] = v;
        g_sl_nc_w[pos] = inv;
        int pos2 = g_rp_nv[v] + atomicAdd(&g_fl_nv[v], 1);
        g_sl_nv_src[pos2] = c;
        g_sl_nv_w[pos2] = inv;
    }
}

// ------------------------------ CSR gather ----------------------------------
extern "C" __global__ void __launch_bounds__(NT)
gather_kernel(const float* __restrict__ src_mat, float* __restrict__ dst,
              const int* __restrict__ rp, const int* __restrict__ sl_src,
              const float* __restrict__ sl_w, int n) {
    long t = (long)blockIdx.x * blockDim.x + threadIdx.x;
    int node = (int)(t >> 5), lane = (int)(t & 31);
    if (node >= n) return;
    int j = rp[node], end = rp[node + 1];
    float4 acc = make_float4(0.f, 0.f, 0.f, 0.f);
    int s_next = 0; float w_next = 0.f;
    if (j < end) { s_next = __ldg(sl_src + j); w_next = __ldg(sl_w + j); }
    while (j < end) {
        int s = s_next; float w = w_next;
        j++;
        if (j < end) { s_next = __ldg(sl_src + j); w_next = __ldg(sl_w + j); }
        float4 x = __ldg(reinterpret_cast<const float4*>(src_mat + (size_t)s * D) + lane);
        acc.x = fmaf(w, x.x, acc.x);
        acc.y = fmaf(w, x.y, acc.y);
        acc.z = fmaf(w, x.z, acc.z);
        acc.w = fmaf(w, x.w, acc.w);
    }
    reinterpret_cast<float4*>(dst + (size_t)node * D)[lane] = acc;
}

// -------------------------------- launch ------------------------------------
extern "C" void kernel_launch(void* const* d_in, const int* in_sizes, int n_in,
                              void* d_out, int out_size) {
    int base = (n_in >= 20) ? 2 : 0;
    const int*   v_edge = (const int*)d_in[base + 0];
    const int*   c_edge = (const int*)d_in[base + 1];
    const int*   p_edge = (const int*)d_in[base + 2];
    const int*   n_edge = (const int*)d_in[base + 3];
    const float* v0     = (const float*)d_in[base + 4];
    const float* c0     = (const float*)d_in[base + 5];
    const float *Wm[4], *Bm[4];
    for (int i = 0; i < 4; i++) {
        Wm[i] = (const float*)d_in[base + 6 + 2 * i];
        Bm[i] = (const float*)d_in[base + 7 + 2 * i];
    }
    const float* cuW = (const float*)d_in[base + 14];
    const float* cub = (const float*)d_in[base + 15];
    const float* vuW = (const float*)d_in[base + 16];
    const float* vub = (const float*)d_in[base + 17];

    const int Eh = in_sizes[base + 2];
    const int V  = in_sizes[base + 4] / D;
    const int C  = in_sizes[base + 5] / D;

    void* p;
    float *t_pv2c, *t_nv2c, *t_pc2v, *t_nc2v, *agg_c, *agg_v;
    int *degi_pv, *degi_nv, *degi_pc, *degi_nc;
    int *rp_pc, *rp_nc, *rp_pv, *rp_nv;
    int *fl_pc, *fl_nc, *fl_pv, *fl_nv;
    int *sl_pc_s, *sl_nc_s, *sl_pv_s, *sl_nv_s;
    float *sl_pc_w, *sl_nc_w, *sl_pv_w, *sl_nv_w;
    unsigned char *img_mlp, *img_cu, *img_vu;
    cudaGetSymbolAddress(&p, g_t_pv2c); t_pv2c = (float*)p;
    cudaGetSymbolAddress(&p, g_t_nv2c); t_nv2c = (float*)p;
    cudaGetSymbolAddress(&p, g_t_pc2v); t_pc2v = (float*)p;
    cudaGetSymbolAddress(&p, g_t_nc2v); t_nc2v = (float*)p;
    cudaGetSymbolAddress(&p, g_agg_c);  agg_c  = (float*)p;
    cudaGetSymbolAddress(&p, g_agg_v);  agg_v  = (float*)p;
    cudaGetSymbolAddress(&p, g_degi_pv); degi_pv = (int*)p;
    cudaGetSymbolAddress(&p, g_degi_nv); degi_nv = (int*)p;
    cudaGetSymbolAddress(&p, g_degi_pc); degi_pc = (int*)p;
    cudaGetSymbolAddress(&p, g_degi_nc); degi_nc = (int*)p;
    cudaGetSymbolAddress(&p, g_rp_pc); rp_pc = (int*)p;
    cudaGetSymbolAddress(&p, g_rp_nc); rp_nc = (int*)p;
    cudaGetSymbolAddress(&p, g_rp_pv); rp_pv = (int*)p;
    cudaGetSymbolAddress(&p, g_rp_nv); rp_nv = (int*)p;
    cudaGetSymbolAddress(&p, g_fl_pc); fl_pc = (int*)p;
    cudaGetSymbolAddress(&p, g_fl_nc); fl_nc = (int*)p;
    cudaGetSymbolAddress(&p, g_fl_pv); fl_pv = (int*)p;
    cudaGetSymbolAddress(&p, g_fl_nv); fl_nv = (int*)p;
    cudaGetSymbolAddress(&p, g_sl_pc_src); sl_pc_s = (int*)p;
    cudaGetSymbolAddress(&p, g_sl_nc_src); sl_nc_s = (int*)p;
    cudaGetSymbolAddress(&p, g_sl_pv_src); sl_pv_s = (int*)p;
    cudaGetSymbolAddress(&p, g_sl_nv_src); sl_nv_s = (int*)p;
    cudaGetSymbolAddress(&p, g_sl_pc_w); sl_pc_w = (float*)p;
    cudaGetSymbolAddress(&p, g_sl_nc_w); sl_nc_w = (float*)p;
    cudaGetSymbolAddress(&p, g_sl_pv_w); sl_pv_w = (float*)p;
    cudaGetSymbolAddress(&p, g_sl_nv_w); sl_nv_w = (float*)p;
    cudaGetSymbolAddress(&p, g_wimg_mlp); img_mlp = (unsigned char*)p;
    cudaGetSymbolAddress(&p, g_wimg_cu);  img_cu  = (unsigned char*)p;
    cudaGetSymbolAddress(&p, g_wimg_vu);  img_vu  = (unsigned char*)p;

    float* agg_c_p = agg_c;
    float* agg_c_n = agg_c + (size_t)CMAX * D;
    float* agg_v_p = agg_v;
    float* agg_v_n = agg_v + (size_t)VMAX * D;

    float* outv = (float*)d_out;
    float* outc = outv + (size_t)4 * V * D;

    int sms = 148;
    cudaDeviceGetAttribute(&sms, cudaDevAttrMultiProcessorCount, 0);

    cudaFuncSetAttribute(mlp2_mma_kernel,
                         cudaFuncAttributeMaxDynamicSharedMemorySize, MS_TOT);
    cudaFuncSetAttribute(update_mma_kernel,
                         cudaFuncAttributeMaxDynamicSharedMemorySize, US_TOT);

    // ---- prep: degrees -> scan -> CSR fill; weight images ----
    cudaMemsetAsync(degi_pv, 0, (size_t)V * sizeof(int));
    cudaMemsetAsync(degi_nv, 0, (size_t)V * sizeof(int));
    cudaMemsetAsync(degi_pc, 0, (size_t)C * sizeof(int));
    cudaMemsetAsync(degi_nc, 0, (size_t)C * sizeof(int));
    cudaMemsetAsync(fl_pc, 0, (size_t)C * sizeof(int));
    cudaMemsetAsync(fl_nc, 0, (size_t)C * sizeof(int));
    cudaMemsetAsync(fl_pv, 0, (size_t)V * sizeof(int));
    cudaMemsetAsync(fl_nv, 0, (size_t)V * sizeof(int));
    {
        int blk = (2 * Eh + NT - 1) / NT;
        degree_kernel<<<blk, NT>>>(v_edge, c_edge, p_edge, n_edge, Eh);
        scan4_kernel<<<4, 1024>>>(V, C);
        fill_kernel<<<blk, NT>>>(v_edge, c_edge, p_edge, n_edge, Eh);
    }
    for (int i = 0; i < 4; i++)
        wconv_mlp_kernel<<<128, 256>>>(Wm[i], img_mlp + (size_t)i * 2 * 32768);
    wconv_upd_kernel<<<192, 256>>>(cuW, img_cu);
    wconv_upd_kernel<<<192, 256>>>(vuW, img_vu);

    cudaMemcpyAsync(outv, v0, (size_t)V * D * sizeof(float), cudaMemcpyDeviceToDevice);
    cudaMemcpyAsync(outc, c0, (size_t)C * D * sizeof(float), cudaMemcpyDeviceToDevice);

    const int gthC = (int)(((long)C * 32 + NT - 1) / NT);
    const int gthV = (int)(((long)V * 32 + NT - 1) / NT);

    for (int t = 0; t < 3; t++) {
        const float* vin = outv + (size_t)t * V * D;
        const float* cin = outc + (size_t)t * C * D;
        float* vout = outv + (size_t)(t + 1) * V * D;
        float* cout = outc + (size_t)(t + 1) * C * D;

        mlp2_mma_kernel<<<2 * sms, NT, MS_TOT>>>(
            vin, (const uint4*)(img_mlp + 0 * 2 * 32768), Bm[0], t_pv2c, V);
        mlp2_mma_kernel<<<2 * sms, NT, MS_TOT>>>(
            vin, (const uint4*)(img_mlp + 1 * 2 * 32768), Bm[1], t_nv2c, V);
        mlp2_mma_kernel<<<2 * sms, NT, MS_TOT>>>(
            cin, (const uint4*)(img_mlp + 2 * 2 * 32768), Bm[2], t_pc2v, C);
        mlp2_mma_kernel<<<2 * sms, NT, MS_TOT>>>(
            cin, (const uint4*)(img_mlp + 3 * 2 * 32768), Bm[3], t_nc2v, C);

        gather_kernel<<<gthC, NT>>>(t_pv2c, agg_c_p, rp_pc, sl_pc_s, sl_pc_w, C);
        gather_kernel<<<gthC, NT>>>(t_nv2c, agg_c_n, rp_nc, sl_nc_s, sl_nc_w, C);
        gather_kernel<<<gthV, NT>>>(t_pc2v, agg_v_p, rp_pv, sl_pv_s, sl_pv_w, V);
        gather_kernel<<<gthV, NT>>>(t_nc2v, agg_v_n, rp_nv, sl_nv_s, sl_nv_w, V);

        update_mma_kernel<<<sms, NT, US_TOT>>>(
            cin, agg_c_p, agg_c_n, (const uint4*)img_cu, cub, cout, C);
        update_mma_kernel<<<sms, NT, US_TOT>>>(
            vin, agg_v_p, agg_v_n, (const uint4*)img_vu, vub, vout, V);
    }
}

// round 8
// speedup vs baseline: 3.2788x; 1.3074x over previous
#include <cuda_runtime.h>
#include <cuda_fp16.h>
#include <cstdint>

// ---------------------------------------------------------------------------
// GCN_VCG, round 7: pure fp16 single-pass GEMMs (A, B, hidden all fp16-rounded,
// fp32 accumulate). Persistent CTAs, resident fp16 weights, M=64 tiles,
// 8 warps (2m x 4n). CSR gather aggregation.
// Calibrated error model: rel_err ~ sqrt(3) * 2.5e-4 ~ 4e-4 < 1e-3.
// ---------------------------------------------------------------------------

#define D        128
#define NT       256
#define VMAX     50000
#define CMAX     210000
#define EHMAX    315000

// ------------------------- scratch (no runtime alloc) ----------------------
__device__ float g_t_pv2c[(size_t)VMAX * D];
__device__ float g_t_nv2c[(size_t)VMAX * D];
__device__ float g_t_pc2v[(size_t)CMAX * D];
__device__ float g_t_nc2v[(size_t)CMAX * D];
__device__ float g_agg_c[2][(size_t)CMAX * D];
__device__ float g_agg_v[2][(size_t)VMAX * D];
// weight images (fp16, swizzled): mlp = 2 layers x 32KB; upd = 3 x 32KB
__device__ unsigned char g_wimg_mlp[4][2 * 32768];
__device__ unsigned char g_wimg_cu[3 * 32768];
__device__ unsigned char g_wimg_vu[3 * 32768];
// CSR structures (iteration-invariant)
__device__ int   g_degi_pv[VMAX], g_degi_nv[VMAX];
__device__ int   g_degi_pc[CMAX], g_degi_nc[CMAX];
__device__ int   g_rp_pc[CMAX + 1], g_rp_nc[CMAX + 1];
__device__ int   g_rp_pv[VMAX + 1], g_rp_nv[VMAX + 1];
__device__ int   g_fl_pc[CMAX], g_fl_nc[CMAX], g_fl_pv[VMAX], g_fl_nv[VMAX];
__device__ int   g_sl_pc_src[EHMAX], g_sl_nc_src[EHMAX];
__device__ int   g_sl_pv_src[EHMAX], g_sl_nv_src[EHMAX];
__device__ float g_sl_pc_w[EHMAX], g_sl_nc_w[EHMAX];
__device__ float g_sl_pv_w[EHMAX], g_sl_nv_w[EHMAX];

// ------------------------------ helpers ------------------------------------
__device__ __forceinline__ uint32_t smem_u32(const void* p) {
    uint32_t a;
    asm("{ .reg .u64 t; cvta.to.shared.u64 t, %1; cvt.u32.u64 %0, t; }"
        : "=r"(a) : "l"(p));
    return a;
}

// byte offset of fp16 (row r, col c) in a [rows x 128] b16 tile; 256B rows,
// 16B chunks XOR-swizzled by (r&7) for conflict-free ldmatrix.
__device__ __host__ __forceinline__ uint32_t swz(int r, int c) {
    return ((uint32_t)r << 8) + ((uint32_t)(((c >> 3) ^ (r & 7)) & 15) << 4)
         + ((uint32_t)(c & 7) << 1);
}

__device__ __forceinline__ uint32_t pack_h2(float a, float b) {
    __half2 h = __floats2half2_rn(a, b);
    return *reinterpret_cast<uint32_t*>(&h);
}

__device__ __forceinline__ void ldm4(uint32_t addr, uint32_t& d0, uint32_t& d1,
                                     uint32_t& d2, uint32_t& d3) {
    asm volatile("ldmatrix.sync.aligned.m8n8.x4.shared.b16 {%0,%1,%2,%3}, [%4];"
                 : "=r"(d0), "=r"(d1), "=r"(d2), "=r"(d3) : "r"(addr));
}

__device__ __forceinline__ void mma16816(float* c, const uint32_t* a,
                                         const uint32_t* b) {
    asm volatile(
        "mma.sync.aligned.m16n8k16.row.col.f32.f16.f16.f32 "
        "{%0,%1,%2,%3}, {%4,%5,%6,%7}, {%8,%9}, {%0,%1,%2,%3};"
        : "+f"(c[0]), "+f"(c[1]), "+f"(c[2]), "+f"(c[3])
        : "r"(a[0]), "r"(a[1]), "r"(a[2]), "r"(a[3]), "r"(b[0]), "r"(b[1]));
}

__device__ __forceinline__ void cp16(uint32_t saddr, const void* g, bool pred) {
    int sz = pred ? 16 : 0;
    asm volatile("cp.async.cg.shared.global [%0], [%1], 16, %2;"
                 :: "r"(saddr), "l"(g), "r"(sz));
}
#define CP_COMMIT() asm volatile("cp.async.commit_group;" ::: "memory")
#define CP_WAIT0()  asm volatile("cp.async.wait_group 0;" ::: "memory")

// One K=128 GEMM pass: M=64 tile, 8 warps as 2m x 4n, warp tile 32x32.
__device__ __forceinline__ void gemm_pass64(uint32_t sA, uint32_t sW,
                                            float acc[2][4][4],
                                            int wm, int wn, int lane) {
#pragma unroll
    for (int ks = 0; ks < 8; ks++) {
        const int kc = ks * 2;
        uint32_t a[2][4];
#pragma unroll
        for (int s = 0; s < 2; s++) {
            int row = wm * 32 + s * 16 + (lane & 7) + ((lane >> 3) & 1) * 8;
            int chunk = ((kc + (lane >> 4)) ^ (row & 7)) & 15;
            ldm4(sA + row * 256 + chunk * 16, a[s][0], a[s][1], a[s][2], a[s][3]);
        }
        uint32_t b[4][2];
#pragma unroll
        for (int p = 0; p < 2; p++) {
            int row = wn * 32 + p * 16 + (lane & 7) + (lane >> 4) * 8;
            int chunk = ((kc + ((lane >> 3) & 1)) ^ (row & 7)) & 15;
            ldm4(sW + row * 256 + chunk * 16,
                 b[2 * p][0], b[2 * p][1], b[2 * p + 1][0], b[2 * p + 1][1]);
        }
#pragma unroll
        for (int s = 0; s < 2; s++)
#pragma unroll
            for (int nt = 0; nt < 4; nt++)
                mma16816(acc[s][nt], a[s], b[nt]);
    }
}

__device__ __forceinline__ void zero_acc(float acc[2][4][4]) {
#pragma unroll
    for (int s = 0; s < 2; s++)
#pragma unroll
        for (int nt = 0; nt < 4; nt++)
#pragma unroll
            for (int j = 0; j < 4; j++) acc[s][nt][j] = 0.f;
}

// gmem fp32 64-row tile -> fp16 swizzled A tile
__device__ __forceinline__ void load64(const float* __restrict__ X,
                                       char* sm, uint32_t sa,
                                       int row0, int N, int tid) {
#pragma unroll
    for (int i = tid; i < 2048; i += NT) {
        int r = i >> 5, c4 = i & 31, g = row0 + r;
        float4 x = make_float4(0.f, 0.f, 0.f, 0.f);
        if (g < N) x = *reinterpret_cast<const float4*>(X + (size_t)g * D + c4 * 4);
        uint2 h = make_uint2(pack_h2(x.x, x.y), pack_h2(x.z, x.w));
        *reinterpret_cast<uint2*>(sm + sa + swz(r, c4 * 4)) = h;
    }
}

// --------------------------- mlp2 persistent -------------------------------
// smem: [W0 32KB][W1 32KB][A 16KB][bias 1KB] = 82944 B -> 2 CTAs/SM
#define MS_W    0
#define MS_A    65536
#define MS_B    81920
#define MS_TOT  82944

extern "C" __global__ void __launch_bounds__(NT, 2)
mlp2_mma_kernel(const float* __restrict__ X, const uint4* __restrict__ Wimg,
                const float* __restrict__ bias, float* __restrict__ Y, int N) {
    extern __shared__ char sm[];
    const uint32_t sb = smem_u32(sm);
    const int tid = threadIdx.x, wid = tid >> 5, lane = tid & 31;
    const int wm = wid >> 2, wn = wid & 3;
    const int tiles = (N + 63) / 64;
    const int G = gridDim.x;
    float* bs = reinterpret_cast<float*>(sm + MS_B);

#pragma unroll 4
    for (int i = tid; i < 4096; i += NT)      // 64KB resident weights
        cp16(sb + MS_W + i * 16, Wimg + i, true);
    if (tid < 2 * D) bs[tid] = bias[tid];
    CP_COMMIT();
    CP_WAIT0();
    __syncthreads();

    for (int t = blockIdx.x; t < tiles; t += G) {
        const int row0 = t * 64;
        load64(X, sm, MS_A, row0, N, tid);
        __syncthreads();

        float acc[2][4][4];
        zero_acc(acc);
        gemm_pass64(sb + MS_A, sb + MS_W, acc, wm, wn, lane);
        __syncthreads();

        // epilogue 1: bias + relu -> fp16 hidden back into A tile
#pragma unroll
        for (int s = 0; s < 2; s++) {
#pragma unroll
            for (int nt = 0; nt < 4; nt++) {
                int m = wm * 32 + s * 16 + (lane >> 2);
                int n = wn * 32 + nt * 8 + (lane & 3) * 2;
                float b0 = bs[n], b1 = bs[n + 1];
                uint32_t h0 = pack_h2(fmaxf(acc[s][nt][0] + b0, 0.f),
                                      fmaxf(acc[s][nt][1] + b1, 0.f));
                uint32_t h1 = pack_h2(fmaxf(acc[s][nt][2] + b0, 0.f),
                                      fmaxf(acc[s][nt][3] + b1, 0.f));
                *reinterpret_cast<uint32_t*>(sm + MS_A + swz(m, n)) = h0;
                *reinterpret_cast<uint32_t*>(sm + MS_A + swz(m + 8, n)) = h1;
            }
        }
        __syncthreads();

        zero_acc(acc);
        gemm_pass64(sb + MS_A, sb + MS_W + 32768, acc, wm, wn, lane);

        // epilogue 2: bias + fp32 store
#pragma unroll
        for (int s = 0; s < 2; s++) {
#pragma unroll
            for (int nt = 0; nt < 4; nt++) {
                int m = wm * 32 + s * 16 + (lane >> 2);
                int n = wn * 32 + nt * 8 + (lane & 3) * 2;
                float b0 = bs[D + n], b1 = bs[D + n + 1];
                int g0 = row0 + m, g1 = row0 + m + 8;
                if (g0 < N) {
                    float2 o = make_float2(acc[s][nt][0] + b0, acc[s][nt][1] + b1);
                    *reinterpret_cast<float2*>(Y + (size_t)g0 * D + n) = o;
                }
                if (g1 < N) {
                    float2 o = make_float2(acc[s][nt][2] + b0, acc[s][nt][3] + b1);
                    *reinterpret_cast<float2*>(Y + (size_t)g1 * D + n) = o;
                }
            }
        }
        __syncthreads();
    }
}

// --------------------------- update persistent -----------------------------
// smem: [W x3 96KB][A 16KB][bias 512B] = 115200 B
#define US_W    0
#define US_A    98304
#define US_B    114688
#define US_TOT  115200

extern "C" __global__ void __launch_bounds__(NT, 2)
update_mma_kernel(const float* __restrict__ X0, const float* __restrict__ X1,
                  const float* __restrict__ X2, const uint4* __restrict__ Wimg,
                  const float* __restrict__ bias, float* __restrict__ Y, int N) {
    extern __shared__ char sm[];
    const uint32_t sb = smem_u32(sm);
    const int tid = threadIdx.x, wid = tid >> 5, lane = tid & 31;
    const int wm = wid >> 2, wn = wid & 3;
    const int tiles = (N + 63) / 64;
    const int G = gridDim.x;
    float* bs = reinterpret_cast<float*>(sm + US_B);

#pragma unroll 4
    for (int i = tid; i < 6144; i += NT)      // 96KB resident weights
        cp16(sb + US_W + i * 16, Wimg + i, true);
    if (tid < D) bs[tid] = bias[tid];
    CP_COMMIT();
    CP_WAIT0();
    __syncthreads();

    const float* srcs[3] = {X0, X1, X2};

    for (int t = blockIdx.x; t < tiles; t += G) {
        const int row0 = t * 64;
        float acc[2][4][4];
        zero_acc(acc);

#pragma unroll
        for (int s = 0; s < 3; s++) {
            load64(srcs[s], sm, US_A, row0, N, tid);
            __syncthreads();
            gemm_pass64(sb + US_A, sb + US_W + s * 32768, acc, wm, wn, lane);
            __syncthreads();
        }

#pragma unroll
        for (int s = 0; s < 2; s++) {
#pragma unroll
            for (int nt = 0; nt < 4; nt++) {
                int m = wm * 32 + s * 16 + (lane >> 2);
                int n = wn * 32 + nt * 8 + (lane & 3) * 2;
                float b0 = bs[n], b1 = bs[n + 1];
                int g0 = row0 + m, g1 = row0 + m + 8;
                if (g0 < N) {
                    float2 o = make_float2(acc[s][nt][0] + b0, acc[s][nt][1] + b1);
                    *reinterpret_cast<float2*>(Y + (size_t)g0 * D + n) = o;
                }
                if (g1 < N) {
                    float2 o = make_float2(acc[s][nt][2] + b0, acc[s][nt][3] + b1);
                    *reinterpret_cast<float2*>(Y + (size_t)g1 * D + n) = o;
                }
            }
        }
    }
}

// ----------------------- weight image conversion ----------------------------
// W[l][k][n] (x@W) -> per layer: swizzled [n][k] fp16 (32KB)
extern "C" __global__ void wconv_mlp_kernel(const float* __restrict__ W,
                                            unsigned char* __restrict__ img) {
    int t = blockIdx.x * blockDim.x + threadIdx.x;
    if (t >= 2 * 128 * 128) return;
    int l = t >> 14, k = (t >> 7) & 127, n = t & 127;
    __half h = __float2half_rn(W[t]);
    *reinterpret_cast<__half*>(img + (size_t)l * 32768 + swz(n, k)) = h;
}

extern "C" __global__ void wconv_upd_kernel(const float* __restrict__ W,
                                            unsigned char* __restrict__ img) {
    int t = blockIdx.x * blockDim.x + threadIdx.x;
    if (t >= 384 * 128) return;
    int k = t >> 7, n = t & 127;
    int s = k >> 7, kl = k & 127;
    __half h = __float2half_rn(W[t]);
    *reinterpret_cast<__half*>(img + (size_t)s * 32768 + swz(n, kl)) = h;
}

// ------------------------------ CSR build -----------------------------------
extern "C" __global__ void degree_kernel(const int* __restrict__ vE,
                                         const int* __restrict__ cE,
                                         const int* __restrict__ pE,
                                         const int* __restrict__ nE, int Eh) {
    int t = blockIdx.x * blockDim.x + threadIdx.x;
    if (t < Eh) {
        int e = pE[t];
        atomicAdd(&g_degi_pv[vE[e]], 1);
        atomicAdd(&g_degi_pc[cE[e]], 1);
    } else if (t < 2 * Eh) {
        int e = nE[t - Eh];
        atomicAdd(&g_degi_nv[vE[e]], 1);
        atomicAdd(&g_degi_nc[cE[e]], 1);
    }
}

extern "C" __global__ void __launch_bounds__(1024)
scan4_kernel(int V, int C) {
    const int* d; int* r; int n;
    switch (blockIdx.x) {
        case 0:  d = g_degi_pc; r = g_rp_pc; n = C; break;
        case 1:  d = g_degi_nc; r = g_rp_nc; n = C; break;
        case 2:  d = g_degi_pv; r = g_rp_pv; n = V; break;
        default: d = g_degi_nv; r = g_rp_nv; n = V; break;
    }
    __shared__ int wsum[32];
    __shared__ int sh_carry, sh_total;
    int tid = threadIdx.x, lane = tid & 31, wid = tid >> 5;
    if (tid == 0) sh_carry = 0;
    __syncthreads();
    for (int base = 0; base < n; base += 1024) {
        int i = base + tid;
        int v = (i < n) ? d[i] : 0;
        int incl = v;
#pragma unroll
        for (int o = 1; o < 32; o <<= 1) {
            int x = __shfl_up_sync(0xffffffffu, incl, o);
            if (lane >= o) incl += x;
        }
        if (lane == 31) wsum[wid] = incl;
        __syncthreads();
        if (tid < 32) {
            int s = wsum[tid], ip = s;
#pragma unroll
            for (int o = 1; o < 32; o <<= 1) {
                int x = __shfl_up_sync(0xffffffffu, ip, o);
                if (tid >= o) ip += x;
            }
            wsum[tid] = ip - s;
            if (tid == 31) sh_total = ip;
        }
        __syncthreads();
        if (i < n) r[i] = sh_carry + wsum[wid] + incl - v;
        __syncthreads();
        if (tid == 0) sh_carry += sh_total;
        __syncthreads();
    }
    if (tid == 0) r[n] = sh_carry;
}

extern "C" __global__ void fill_kernel(const int* __restrict__ vE,
                                       const int* __restrict__ cE,
                                       const int* __restrict__ pE,
                                       const int* __restrict__ nE, int Eh) {
    int t = blockIdx.x * blockDim.x + threadIdx.x;
    if (t < Eh) {
        int e = pE[t];
        int v = vE[e], c = cE[e];
        float inv = rsqrtf((float)max(g_degi_pv[v], 1) * (float)max(g_degi_pc[c], 1));
        int pos = g_rp_pc[c] + atomicAdd(&g_fl_pc[c], 1);
        g_sl_pc_src[pos] = v;
        g_sl_pc_w[pos] = inv;
        int pos2 = g_rp_pv[v] + atomicAdd(&g_fl_pv[v], 1);
        g_sl_pv_src[pos2] = c;
        g_sl_pv_w[pos2] = inv;
    } else if (t < 2 * Eh) {
        int e = nE[t - Eh];
        int v = vE[e], c = cE[e];
        float inv = rsqrtf((float)max(g_degi_nv[v], 1) * (float)max(g_degi_nc[c], 1));
        int pos = g_rp_nc[c] + atomicAdd(&g_fl_nc[c], 1);
        g_sl_nc_src[pos] = v;
        g_sl_nc_w[pos] = inv;
        int pos2 = g_rp_nv[v] + atomicAdd(&g_fl_nv[v], 1);
        g_sl_nv_src[pos2] = c;
        g_sl_nv_w[pos2] = inv;
    }
}

// ------------------------------ CSR gather ----------------------------------
extern "C" __global__ void __launch_bounds__(NT)
gather_kernel(const float* __restrict__ src_mat, float* __restrict__ dst,
              const int* __restrict__ rp, const int* __restrict__ sl_src,
              const float* __restrict__ sl_w, int n) {
    long t = (long)blockIdx.x * blockDim.x + threadIdx.x;
    int node = (int)(t >> 5), lane = (int)(t & 31);
    if (node >= n) return;
    int j = rp[node], end = rp[node + 1];
    float4 acc = make_float4(0.f, 0.f, 0.f, 0.f);
    int s_next = 0; float w_next = 0.f;
    if (j < end) { s_next = __ldg(sl_src + j); w_next = __ldg(sl_w + j); }
    while (j < end) {
        int s = s_next; float w = w_next;
        j++;
        if (j < end) { s_next = __ldg(sl_src + j); w_next = __ldg(sl_w + j); }
        float4 x = __ldg(reinterpret_cast<const float4*>(src_mat + (size_t)s * D) + lane);
        acc.x = fmaf(w, x.x, acc.x);
        acc.y = fmaf(w, x.y, acc.y);
        acc.z = fmaf(w, x.z, acc.z);
        acc.w = fmaf(w, x.w, acc.w);
    }
    reinterpret_cast<float4*>(dst + (size_t)node * D)[lane] = acc;
}

// -------------------------------- launch ------------------------------------
extern "C" void kernel_launch(void* const* d_in, const int* in_sizes, int n_in,
                              void* d_out, int out_size) {
    int base = (n_in >= 20) ? 2 : 0;
    const int*   v_edge = (const int*)d_in[base + 0];
    const int*   c_edge = (const int*)d_in[base + 1];
    const int*   p_edge = (const int*)d_in[base + 2];
    const int*   n_edge = (const int*)d_in[base + 3];
    const float* v0     = (const float*)d_in[base + 4];
    const float* c0     = (const float*)d_in[base + 5];
    const float *Wm[4], *Bm[4];
    for (int i = 0; i < 4; i++) {
        Wm[i] = (const float*)d_in[base + 6 + 2 * i];
        Bm[i] = (const float*)d_in[base + 7 + 2 * i];
    }
    const float* cuW = (const float*)d_in[base + 14];
    const float* cub = (const float*)d_in[base + 15];
    const float* vuW = (const float*)d_in[base + 16];
    const float* vub = (const float*)d_in[base + 17];

    const int Eh = in_sizes[base + 2];
    const int V  = in_sizes[base + 4] / D;
    const int C  = in_sizes[base + 5] / D;

    void* p;
    float *t_pv2c, *t_nv2c, *t_pc2v, *t_nc2v, *agg_c, *agg_v;
    int *degi_pv, *degi_nv, *degi_pc, *degi_nc;
    int *rp_pc, *rp_nc, *rp_pv, *rp_nv;
    int *fl_pc, *fl_nc, *fl_pv, *fl_nv;
    int *sl_pc_s, *sl_nc_s, *sl_pv_s, *sl_nv_s;
    float *sl_pc_w, *sl_nc_w, *sl_pv_w, *sl_nv_w;
    unsigned char *img_mlp, *img_cu, *img_vu;
    cudaGetSymbolAddress(&p, g_t_pv2c); t_pv2c = (float*)p;
    cudaGetSymbolAddress(&p, g_t_nv2c); t_nv2c = (float*)p;
    cudaGetSymbolAddress(&p, g_t_pc2v); t_pc2v = (float*)p;
    cudaGetSymbolAddress(&p, g_t_nc2v); t_nc2v = (float*)p;
    cudaGetSymbolAddress(&p, g_agg_c);  agg_c  = (float*)p;
    cudaGetSymbolAddress(&p, g_agg_v);  agg_v  = (float*)p;
    cudaGetSymbolAddress(&p, g_degi_pv); degi_pv = (int*)p;
    cudaGetSymbolAddress(&p, g_degi_nv); degi_nv = (int*)p;
    cudaGetSymbolAddress(&p, g_degi_pc); degi_pc = (int*)p;
    cudaGetSymbolAddress(&p, g_degi_nc); degi_nc = (int*)p;
    cudaGetSymbolAddress(&p, g_rp_pc); rp_pc = (int*)p;
    cudaGetSymbolAddress(&p, g_rp_nc); rp_nc = (int*)p;
    cudaGetSymbolAddress(&p, g_rp_pv); rp_pv = (int*)p;
    cudaGetSymbolAddress(&p, g_rp_nv); rp_nv = (int*)p;
    cudaGetSymbolAddress(&p, g_fl_pc); fl_pc = (int*)p;
    cudaGetSymbolAddress(&p, g_fl_nc); fl_nc = (int*)p;
    cudaGetSymbolAddress(&p, g_fl_pv); fl_pv = (int*)p;
    cudaGetSymbolAddress(&p, g_fl_nv); fl_nv = (int*)p;
    cudaGetSymbolAddress(&p, g_sl_pc_src); sl_pc_s = (int*)p;
    cudaGetSymbolAddress(&p, g_sl_nc_src); sl_nc_s = (int*)p;
    cudaGetSymbolAddress(&p, g_sl_pv_src); sl_pv_s = (int*)p;
    cudaGetSymbolAddress(&p, g_sl_nv_src); sl_nv_s = (int*)p;
    cudaGetSymbolAddress(&p, g_sl_pc_w); sl_pc_w = (float*)p;
    cudaGetSymbolAddress(&p, g_sl_nc_w); sl_nc_w = (float*)p;
    cudaGetSymbolAddress(&p, g_sl_pv_w); sl_pv_w = (float*)p;
    cudaGetSymbolAddress(&p, g_sl_nv_w); sl_nv_w = (float*)p;
    cudaGetSymbolAddress(&p, g_wimg_mlp); img_mlp = (unsigned char*)p;
    cudaGetSymbolAddress(&p, g_wimg_cu);  img_cu  = (unsigned char*)p;
    cudaGetSymbolAddress(&p, g_wimg_vu);  img_vu  = (unsigned char*)p;

    float* agg_c_p = agg_c;
    float* agg_c_n = agg_c + (size_t)CMAX * D;
    float* agg_v_p = agg_v;
    float* agg_v_n = agg_v + (size_t)VMAX * D;

    float* outv = (float*)d_out;
    float* outc = outv + (size_t)4 * V * D;

    int sms = 148;
    cudaDeviceGetAttribute(&sms, cudaDevAttrMultiProcessorCount, 0);

    cudaFuncSetAttribute(mlp2_mma_kernel,
                         cudaFuncAttributeMaxDynamicSharedMemorySize, MS_TOT);
    cudaFuncSetAttribute(update_mma_kernel,
                         cudaFuncAttributeMaxDynamicSharedMemorySize, US_TOT);

    // ---- prep: degrees -> scan -> CSR fill; weight images ----
    cudaMemsetAsync(degi_pv, 0, (size_t)V * sizeof(int));
    cudaMemsetAsync(degi_nv, 0, (size_t)V * sizeof(int));
    cudaMemsetAsync(degi_pc, 0, (size_t)C * sizeof(int));
    cudaMemsetAsync(degi_nc, 0, (size_t)C * sizeof(int));
    cudaMemsetAsync(fl_pc, 0, (size_t)C * sizeof(int));
    cudaMemsetAsync(fl_nc, 0, (size_t)C * sizeof(int));
    cudaMemsetAsync(fl_pv, 0, (size_t)V * sizeof(int));
    cudaMemsetAsync(fl_nv, 0, (size_t)V * sizeof(int));
    {
        int blk = (2 * Eh + NT - 1) / NT;
        degree_kernel<<<blk, NT>>>(v_edge, c_edge, p_edge, n_edge, Eh);
        scan4_kernel<<<4, 1024>>>(V, C);
        fill_kernel<<<blk, NT>>>(v_edge, c_edge, p_edge, n_edge, Eh);
    }
    for (int i = 0; i < 4; i++)
        wconv_mlp_kernel<<<128, 256>>>(Wm[i], img_mlp + (size_t)i * 2 * 32768);
    wconv_upd_kernel<<<192, 256>>>(cuW, img_cu);
    wconv_upd_kernel<<<192, 256>>>(vuW, img_vu);

    cudaMemcpyAsync(outv, v0, (size_t)V * D * sizeof(float), cudaMemcpyDeviceToDevice);
    cudaMemcpyAsync(outc, c0, (size_t)C * D * sizeof(float), cudaMemcpyDeviceToDevice);

    const int gthC = (int)(((long)C * 32 + NT - 1) / NT);
    const int gthV = (int)(((long)V * 32 + NT - 1) / NT);

    for (int t = 0; t < 3; t++) {
        const float* vin = outv + (size_t)t * V * D;
        const float* cin = outc + (size_t)t * C * D;
        float* vout = outv + (size_t)(t + 1) * V * D;
        float* cout = outc + (size_t)(t + 1) * C * D;

        mlp2_mma_kernel<<<2 * sms, NT, MS_TOT>>>(
            vin, (const uint4*)(img_mlp + 0 * 2 * 32768), Bm[0], t_pv2c, V);
        mlp2_mma_kernel<<<2 * sms, NT, MS_TOT>>>(
            vin, (const uint4*)(img_mlp + 1 * 2 * 32768), Bm[1], t_nv2c, V);
        mlp2_mma_kernel<<<2 * sms, NT, MS_TOT>>>(
            cin, (const uint4*)(img_mlp + 2 * 2 * 32768), Bm[2], t_pc2v, C);
        mlp2_mma_kernel<<<2 * sms, NT, MS_TOT>>>(
            cin, (const uint4*)(img_mlp + 3 * 2 * 32768), Bm[3], t_nc2v, C);

        gather_kernel<<<gthC, NT>>>(t_pv2c, agg_c_p, rp_pc, sl_pc_s, sl_pc_w, C);
        gather_kernel<<<gthC, NT>>>(t_nv2c, agg_c_n, rp_nc, sl_nc_s, sl_nc_w, C);
        gather_kernel<<<gthV, NT>>>(t_pc2v, agg_v_p, rp_pv, sl_pv_s, sl_pv_w, V);
        gather_kernel<<<gthV, NT>>>(t_nc2v, agg_v_n, rp_nv, sl_nv_s, sl_nv_w, V);

        update_mma_kernel<<<2 * sms, NT, US_TOT>>>(
            cin, agg_c_p, agg_c_n, (const uint4*)img_cu, cub, cout, C);
        update_mma_kernel<<<2 * sms, NT, US_TOT>>>(
            vin, agg_v_p, agg_v_n, (const uint4*)img_vu, vub, vout, V);
    }
}

// round 9
// speedup vs baseline: 3.7015x; 1.1289x over previous
#include <cuda_runtime.h>
#include <cuda_fp16.h>
#include <cstdint>

// ---------------------------------------------------------------------------
// GCN_VCG, round 9: fp16 end-to-end intermediates.
//  - GEMMs: pure fp16 single-pass mma.sync, persistent CTAs, resident weights.
//  - MLP outputs (t_*) and aggregates (agg_*) stored fp16 (halves gather +
//    epilogue traffic; update GEMM rounded them to fp16 anyway).
//  - CSR gather: 16-lane groups (2 nodes/warp), uint4 loads.
// ---------------------------------------------------------------------------

#define D        128
#define NT       256
#define VMAX     50000
#define CMAX     210000
#define EHMAX    315000

// ------------------------- scratch (no runtime alloc) ----------------------
__device__ unsigned short g_t_pv2c[(size_t)VMAX * D];
__device__ unsigned short g_t_nv2c[(size_t)VMAX * D];
__device__ unsigned short g_t_pc2v[(size_t)CMAX * D];
__device__ unsigned short g_t_nc2v[(size_t)CMAX * D];
__device__ unsigned short g_agg_c[2][(size_t)CMAX * D];
__device__ unsigned short g_agg_v[2][(size_t)VMAX * D];
// weight images (fp16, swizzled): mlp = 2 layers x 32KB; upd = 3 x 32KB
__device__ unsigned char g_wimg_mlp[4][2 * 32768];
__device__ unsigned char g_wimg_cu[3 * 32768];
__device__ unsigned char g_wimg_vu[3 * 32768];
// CSR structures (iteration-invariant)
__device__ int   g_degi_pv[VMAX], g_degi_nv[VMAX];
__device__ int   g_degi_pc[CMAX], g_degi_nc[CMAX];
__device__ int   g_rp_pc[CMAX + 1], g_rp_nc[CMAX + 1];
__device__ int   g_rp_pv[VMAX + 1], g_rp_nv[VMAX + 1];
__device__ int   g_fl_pc[CMAX], g_fl_nc[CMAX], g_fl_pv[VMAX], g_fl_nv[VMAX];
__device__ int   g_sl_pc_src[EHMAX], g_sl_nc_src[EHMAX];
__device__ int   g_sl_pv_src[EHMAX], g_sl_nv_src[EHMAX];
__device__ float g_sl_pc_w[EHMAX], g_sl_nc_w[EHMAX];
__device__ float g_sl_pv_w[EHMAX], g_sl_nv_w[EHMAX];

// ------------------------------ helpers ------------------------------------
__device__ __forceinline__ uint32_t smem_u32(const void* p) {
    uint32_t a;
    asm("{ .reg .u64 t; cvta.to.shared.u64 t, %1; cvt.u32.u64 %0, t; }"
        : "=r"(a) : "l"(p));
    return a;
}

// byte offset of fp16 (row r, col c) in a [rows x 128] b16 tile; 256B rows,
// 16B chunks XOR-swizzled by (r&7) for conflict-free ldmatrix.
__device__ __host__ __forceinline__ uint32_t swz(int r, int c) {
    return ((uint32_t)r << 8) + ((uint32_t)(((c >> 3) ^ (r & 7)) & 15) << 4)
         + ((uint32_t)(c & 7) << 1);
}

__device__ __forceinline__ uint32_t pack_h2(float a, float b) {
    __half2 h = __floats2half2_rn(a, b);
    return *reinterpret_cast<uint32_t*>(&h);
}

__device__ __forceinline__ float2 unpack_h2(uint32_t u) {
    return __half22float2(*reinterpret_cast<__half2*>(&u));
}

__device__ __forceinline__ void ldm4(uint32_t addr, uint32_t& d0, uint32_t& d1,
                                     uint32_t& d2, uint32_t& d3) {
    asm volatile("ldmatrix.sync.aligned.m8n8.x4.shared.b16 {%0,%1,%2,%3}, [%4];"
                 : "=r"(d0), "=r"(d1), "=r"(d2), "=r"(d3) : "r"(addr));
}

__device__ __forceinline__ void mma16816(float* c, const uint32_t* a,
                                         const uint32_t* b) {
    asm volatile(
        "mma.sync.aligned.m16n8k16.row.col.f32.f16.f16.f32 "
        "{%0,%1,%2,%3}, {%4,%5,%6,%7}, {%8,%9}, {%0,%1,%2,%3};"
        : "+f"(c[0]), "+f"(c[1]), "+f"(c[2]), "+f"(c[3])
        : "r"(a[0]), "r"(a[1]), "r"(a[2]), "r"(a[3]), "r"(b[0]), "r"(b[1]));
}

__device__ __forceinline__ void cp16(uint32_t saddr, const void* g, bool pred) {
    int sz = pred ? 16 : 0;
    asm volatile("cp.async.cg.shared.global [%0], [%1], 16, %2;"
                 :: "r"(saddr), "l"(g), "r"(sz));
}
#define CP_COMMIT() asm volatile("cp.async.commit_group;" ::: "memory")
#define CP_WAIT0()  asm volatile("cp.async.wait_group 0;" ::: "memory")

// One K=128 GEMM pass: M=64 tile, 8 warps as 2m x 4n, warp tile 32x32.
__device__ __forceinline__ void gemm_pass64(uint32_t sA, uint32_t sW,
                                            float acc[2][4][4],
                                            int wm, int wn, int lane) {
#pragma unroll
    for (int ks = 0; ks < 8; ks++) {
        const int kc = ks * 2;
        uint32_t a[2][4];
#pragma unroll
        for (int s = 0; s < 2; s++) {
            int row = wm * 32 + s * 16 + (lane & 7) + ((lane >> 3) & 1) * 8;
            int chunk = ((kc + (lane >> 4)) ^ (row & 7)) & 15;
            ldm4(sA + row * 256 + chunk * 16, a[s][0], a[s][1], a[s][2], a[s][3]);
        }
        uint32_t b[4][2];
#pragma unroll
        for (int p = 0; p < 2; p++) {
            int row = wn * 32 + p * 16 + (lane & 7) + (lane >> 4) * 8;
            int chunk = ((kc + ((lane >> 3) & 1)) ^ (row & 7)) & 15;
            ldm4(sW + row * 256 + chunk * 16,
                 b[2 * p][0], b[2 * p][1], b[2 * p + 1][0], b[2 * p + 1][1]);
        }
#pragma unroll
        for (int s = 0; s < 2; s++)
#pragma unroll
            for (int nt = 0; nt < 4; nt++)
                mma16816(acc[s][nt], a[s], b[nt]);
    }
}

__device__ __forceinline__ void zero_acc(float acc[2][4][4]) {
#pragma unroll
    for (int s = 0; s < 2; s++)
#pragma unroll
        for (int nt = 0; nt < 4; nt++)
#pragma unroll
            for (int j = 0; j < 4; j++) acc[s][nt][j] = 0.f;
}

// gmem fp32 64-row tile -> fp16 swizzled A tile
__device__ __forceinline__ void load64_f32(const float* __restrict__ X,
                                           char* sm, uint32_t sa,
                                           int row0, int N, int tid) {
#pragma unroll
    for (int i = tid; i < 2048; i += NT) {
        int r = i >> 5, c4 = i & 31, g = row0 + r;
        float4 x = make_float4(0.f, 0.f, 0.f, 0.f);
        if (g < N) x = *reinterpret_cast<const float4*>(X + (size_t)g * D + c4 * 4);
        uint2 h = make_uint2(pack_h2(x.x, x.y), pack_h2(x.z, x.w));
        *reinterpret_cast<uint2*>(sm + sa + swz(r, c4 * 4)) = h;
    }
}

// gmem fp16 64-row tile -> swizzled A tile (no conversion)
__device__ __forceinline__ void load64_f16(const unsigned short* __restrict__ X,
                                           char* sm, uint32_t sa,
                                           int row0, int N, int tid) {
#pragma unroll
    for (int i = tid; i < 2048; i += NT) {
        int r = i >> 5, c4 = i & 31, g = row0 + r;
        uint2 h = make_uint2(0u, 0u);
        if (g < N) h = *reinterpret_cast<const uint2*>(X + (size_t)g * D + c4 * 4);
        *reinterpret_cast<uint2*>(sm + sa + swz(r, c4 * 4)) = h;
    }
}

// --------------------------- mlp2 persistent -------------------------------
// smem: [W0 32KB][W1 32KB][A 16KB][bias 1KB] = 82944 B -> 2 CTAs/SM
#define MS_W    0
#define MS_A    65536
#define MS_B    81920
#define MS_TOT  82944

extern "C" __global__ void __launch_bounds__(NT, 2)
mlp2_mma_kernel(const float* __restrict__ X, const uint4* __restrict__ Wimg,
                const float* __restrict__ bias, unsigned short* __restrict__ Y,
                int N) {
    extern __shared__ char sm[];
    const uint32_t sb = smem_u32(sm);
    const int tid = threadIdx.x, wid = tid >> 5, lane = tid & 31;
    const int wm = wid >> 2, wn = wid & 3;
    const int tiles = (N + 63) / 64;
    const int G = gridDim.x;
    float* bs = reinterpret_cast<float*>(sm + MS_B);

#pragma unroll 4
    for (int i = tid; i < 4096; i += NT)      // 64KB resident weights
        cp16(sb + MS_W + i * 16, Wimg + i, true);
    if (tid < 2 * D) bs[tid] = bias[tid];
    CP_COMMIT();
    CP_WAIT0();
    __syncthreads();

    for (int t = blockIdx.x; t < tiles; t += G) {
        const int row0 = t * 64;
        load64_f32(X, sm, MS_A, row0, N, tid);
        __syncthreads();

        float acc[2][4][4];
        zero_acc(acc);
        gemm_pass64(sb + MS_A, sb + MS_W, acc, wm, wn, lane);
        __syncthreads();

        // epilogue 1: bias + relu -> fp16 hidden back into A tile
#pragma unroll
        for (int s = 0; s < 2; s++) {
#pragma unroll
            for (int nt = 0; nt < 4; nt++) {
                int m = wm * 32 + s * 16 + (lane >> 2);
                int n = wn * 32 + nt * 8 + (lane & 3) * 2;
                float b0 = bs[n], b1 = bs[n + 1];
                uint32_t h0 = pack_h2(fmaxf(acc[s][nt][0] + b0, 0.f),
                                      fmaxf(acc[s][nt][1] + b1, 0.f));
                uint32_t h1 = pack_h2(fmaxf(acc[s][nt][2] + b0, 0.f),
                                      fmaxf(acc[s][nt][3] + b1, 0.f));
                *reinterpret_cast<uint32_t*>(sm + MS_A + swz(m, n)) = h0;
                *reinterpret_cast<uint32_t*>(sm + MS_A + swz(m + 8, n)) = h1;
            }
        }
        __syncthreads();

        zero_acc(acc);
        gemm_pass64(sb + MS_A, sb + MS_W + 32768, acc, wm, wn, lane);

        // epilogue 2: bias + fp16 store
#pragma unroll
        for (int s = 0; s < 2; s++) {
#pragma unroll
            for (int nt = 0; nt < 4; nt++) {
                int m = wm * 32 + s * 16 + (lane >> 2);
                int n = wn * 32 + nt * 8 + (lane & 3) * 2;
                float b0 = bs[D + n], b1 = bs[D + n + 1];
                int g0 = row0 + m, g1 = row0 + m + 8;
                if (g0 < N)
                    *reinterpret_cast<uint32_t*>(Y + (size_t)g0 * D + n) =
                        pack_h2(acc[s][nt][0] + b0, acc[s][nt][1] + b1);
                if (g1 < N)
                    *reinterpret_cast<uint32_t*>(Y + (size_t)g1 * D + n) =
                        pack_h2(acc[s][nt][2] + b0, acc[s][nt][3] + b1);
            }
        }
        __syncthreads();
    }
}

// --------------------------- update persistent -----------------------------
// smem: [W x3 96KB][A 16KB][bias 512B] = 115200 B
#define US_W    0
#define US_A    98304
#define US_B    114688
#define US_TOT  115200

extern "C" __global__ void __launch_bounds__(NT, 2)
update_mma_kernel(const float* __restrict__ X0,
                  const unsigned short* __restrict__ X1,
                  const unsigned short* __restrict__ X2,
                  const uint4* __restrict__ Wimg,
                  const float* __restrict__ bias, float* __restrict__ Y, int N) {
    extern __shared__ char sm[];
    const uint32_t sb = smem_u32(sm);
    const int tid = threadIdx.x, wid = tid >> 5, lane = tid & 31;
    const int wm = wid >> 2, wn = wid & 3;
    const int tiles = (N + 63) / 64;
    const int G = gridDim.x;
    float* bs = reinterpret_cast<float*>(sm + US_B);

#pragma unroll 4
    for (int i = tid; i < 6144; i += NT)      // 96KB resident weights
        cp16(sb + US_W + i * 16, Wimg + i, true);
    if (tid < D) bs[tid] = bias[tid];
    CP_COMMIT();
    CP_WAIT0();
    __syncthreads();

    for (int t = blockIdx.x; t < tiles; t += G) {
        const int row0 = t * 64;
        float acc[2][4][4];
        zero_acc(acc);

        load64_f32(X0, sm, US_A, row0, N, tid);
        __syncthreads();
        gemm_pass64(sb + US_A, sb + US_W, acc, wm, wn, lane);
        __syncthreads();

        load64_f16(X1, sm, US_A, row0, N, tid);
        __syncthreads();
        gemm_pass64(sb + US_A, sb + US_W + 32768, acc, wm, wn, lane);
        __syncthreads();

        load64_f16(X2, sm, US_A, row0, N, tid);
        __syncthreads();
        gemm_pass64(sb + US_A, sb + US_W + 65536, acc, wm, wn, lane);
        __syncthreads();

#pragma unroll
        for (int s = 0; s < 2; s++) {
#pragma unroll
            for (int nt = 0; nt < 4; nt++) {
                int m = wm * 32 + s * 16 + (lane >> 2);
                int n = wn * 32 + nt * 8 + (lane & 3) * 2;
                float b0 = bs[n], b1 = bs[n + 1];
                int g0 = row0 + m, g1 = row0 + m + 8;
                if (g0 < N) {
                    float2 o = make_float2(acc[s][nt][0] + b0, acc[s][nt][1] + b1);
                    *reinterpret_cast<float2*>(Y + (size_t)g0 * D + n) = o;
                }
                if (g1 < N) {
                    float2 o = make_float2(acc[s][nt][2] + b0, acc[s][nt][3] + b1);
                    *reinterpret_cast<float2*>(Y + (size_t)g1 * D + n) = o;
                }
            }
        }
    }
}

// ----------------------- weight image conversion ----------------------------
extern "C" __global__ void wconv_mlp_kernel(const float* __restrict__ W,
                                            unsigned char* __restrict__ img) {
    int t = blockIdx.x * blockDim.x + threadIdx.x;
    if (t >= 2 * 128 * 128) return;
    int l = t >> 14, k = (t >> 7) & 127, n = t & 127;
    __half h = __float2half_rn(W[t]);
    *reinterpret_cast<__half*>(img + (size_t)l * 32768 + swz(n, k)) = h;
}

extern "C" __global__ void wconv_upd_kernel(const float* __restrict__ W,
                                            unsigned char* __restrict__ img) {
    int t = blockIdx.x * blockDim.x + threadIdx.x;
    if (t >= 384 * 128) return;
    int k = t >> 7, n = t & 127;
    int s = k >> 7, kl = k & 127;
    __half h = __float2half_rn(W[t]);
    *reinterpret_cast<__half*>(img + (size_t)s * 32768 + swz(n, kl)) = h;
}

// ------------------------------ CSR build -----------------------------------
extern "C" __global__ void degree_kernel(const int* __restrict__ vE,
                                         const int* __restrict__ cE,
                                         const int* __restrict__ pE,
                                         const int* __restrict__ nE, int Eh) {
    int t = blockIdx.x * blockDim.x + threadIdx.x;
    if (t < Eh) {
        int e = pE[t];
        atomicAdd(&g_degi_pv[vE[e]], 1);
        atomicAdd(&g_degi_pc[cE[e]], 1);
    } else if (t < 2 * Eh) {
        int e = nE[t - Eh];
        atomicAdd(&g_degi_nv[vE[e]], 1);
        atomicAdd(&g_degi_nc[cE[e]], 1);
    }
}

extern "C" __global__ void __launch_bounds__(1024)
scan4_kernel(int V, int C) {
    const int* d; int* r; int n;
    switch (blockIdx.x) {
        case 0:  d = g_degi_pc; r = g_rp_pc; n = C; break;
        case 1:  d = g_degi_nc; r = g_rp_nc; n = C; break;
        case 2:  d = g_degi_pv; r = g_rp_pv; n = V; break;
        default: d = g_degi_nv; r = g_rp_nv; n = V; break;
    }
    __shared__ int wsum[32];
    __shared__ int sh_carry, sh_total;
    int tid = threadIdx.x, lane = tid & 31, wid = tid >> 5;
    if (tid == 0) sh_carry = 0;
    __syncthreads();
    for (int base = 0; base < n; base += 1024) {
        int i = base + tid;
        int v = (i < n) ? d[i] : 0;
        int incl = v;
#pragma unroll
        for (int o = 1; o < 32; o <<= 1) {
            int x = __shfl_up_sync(0xffffffffu, incl, o);
            if (lane >= o) incl += x;
        }
        if (lane == 31) wsum[wid] = incl;
        __syncthreads();
        if (tid < 32) {
            int s = wsum[tid], ip = s;
#pragma unroll
            for (int o = 1; o < 32; o <<= 1) {
                int x = __shfl_up_sync(0xffffffffu, ip, o);
                if (tid >= o) ip += x;
            }
            wsum[tid] = ip - s;
            if (tid == 31) sh_total = ip;
        }
        __syncthreads();
        if (i < n) r[i] = sh_carry + wsum[wid] + incl - v;
        __syncthreads();
        if (tid == 0) sh_carry += sh_total;
        __syncthreads();
    }
    if (tid == 0) r[n] = sh_carry;
}

extern "C" __global__ void fill_kernel(const int* __restrict__ vE,
                                       const int* __restrict__ cE,
                                       const int* __restrict__ pE,
                                       const int* __restrict__ nE, int Eh) {
    int t = blockIdx.x * blockDim.x + threadIdx.x;
    if (t < Eh) {
        int e = pE[t];
        int v = vE[e], c = cE[e];
        float inv = rsqrtf((float)max(g_degi_pv[v], 1) * (float)max(g_degi_pc[c], 1));
        int pos = g_rp_pc[c] + atomicAdd(&g_fl_pc[c], 1);
        g_sl_pc_src[pos] = v;
        g_sl_pc_w[pos] = inv;
        int pos2 = g_rp_pv[v] + atomicAdd(&g_fl_pv[v], 1);
        g_sl_pv_src[pos2] = c;
        g_sl_pv_w[pos2] = inv;
    } else if (t < 2 * Eh) {
        int e = nE[t - Eh];
        int v = vE[e], c = cE[e];
        float inv = rsqrtf((float)max(g_degi_nv[v], 1) * (float)max(g_degi_nc[c], 1));
        int pos = g_rp_nc[c] + atomicAdd(&g_fl_nc[c], 1);
        g_sl_nc_src[pos] = v;
        g_sl_nc_w[pos] = inv;
        int pos2 = g_rp_nv[v] + atomicAdd(&g_fl_nv[v], 1);
        g_sl_nv_src[pos2] = c;
        g_sl_nv_w[pos2] = inv;
    }
}

// ------------------------------ CSR gather ----------------------------------
// 16-lane group per destination node (2 nodes/warp); lane covers uint4 = 8 fp16.
extern "C" __global__ void __launch_bounds__(NT)
gather_kernel(const unsigned short* __restrict__ src_mat,
              unsigned short* __restrict__ dst,
              const int* __restrict__ rp, const int* __restrict__ sl_src,
              const float* __restrict__ sl_w, int n) {
    long t = (long)blockIdx.x * blockDim.x + threadIdx.x;
    int node = (int)(t >> 4), sub = (int)(t & 15);
    if (node >= n) return;
    int j = rp[node], end = rp[node + 1];
    float acc[8] = {0.f, 0.f, 0.f, 0.f, 0.f, 0.f, 0.f, 0.f};
    int s_next = 0; float w_next = 0.f;
    if (j < end) { s_next = __ldg(sl_src + j); w_next = __ldg(sl_w + j); }
    while (j < end) {
        int s = s_next; float w = w_next;
        j++;
        if (j < end) { s_next = __ldg(sl_src + j); w_next = __ldg(sl_w + j); }
        uint4 x = __ldg(reinterpret_cast<const uint4*>(src_mat + (size_t)s * D) + sub);
        float2 f0 = unpack_h2(x.x), f1 = unpack_h2(x.y);
        float2 f2 = unpack_h2(x.z), f3 = unpack_h2(x.w);
        acc[0] = fmaf(w, f0.x, acc[0]); acc[1] = fmaf(w, f0.y, acc[1]);
        acc[2] = fmaf(w, f1.x, acc[2]); acc[3] = fmaf(w, f1.y, acc[3]);
        acc[4] = fmaf(w, f2.x, acc[4]); acc[5] = fmaf(w, f2.y, acc[5]);
        acc[6] = fmaf(w, f3.x, acc[6]); acc[7] = fmaf(w, f3.y, acc[7]);
    }
    uint4 o;
    o.x = pack_h2(acc[0], acc[1]);
    o.y = pack_h2(acc[2], acc[3]);
    o.z = pack_h2(acc[4], acc[5]);
    o.w = pack_h2(acc[6], acc[7]);
    reinterpret_cast<uint4*>(dst + (size_t)node * D)[sub] = o;
}

// -------------------------------- launch ------------------------------------
extern "C" void kernel_launch(void* const* d_in, const int* in_sizes, int n_in,
                              void* d_out, int out_size) {
    int base = (n_in >= 20) ? 2 : 0;
    const int*   v_edge = (const int*)d_in[base + 0];
    const int*   c_edge = (const int*)d_in[base + 1];
    const int*   p_edge = (const int*)d_in[base + 2];
    const int*   n_edge = (const int*)d_in[base + 3];
    const float* v0     = (const float*)d_in[base + 4];
    const float* c0     = (const float*)d_in[base + 5];
    const float *Wm[4], *Bm[4];
    for (int i = 0; i < 4; i++) {
        Wm[i] = (const float*)d_in[base + 6 + 2 * i];
        Bm[i] = (const float*)d_in[base + 7 + 2 * i];
    }
    const float* cuW = (const float*)d_in[base + 14];
    const float* cub = (const float*)d_in[base + 15];
    const float* vuW = (const float*)d_in[base + 16];
    const float* vub = (const float*)d_in[base + 17];

    const int Eh = in_sizes[base + 2];
    const int V  = in_sizes[base + 4] / D;
    const int C  = in_sizes[base + 5] / D;

    void* p;
    unsigned short *t_pv2c, *t_nv2c, *t_pc2v, *t_nc2v, *agg_c, *agg_v;
    int *degi_pv, *degi_nv, *degi_pc, *degi_nc;
    int *rp_pc, *rp_nc, *rp_pv, *rp_nv;
    int *fl_pc, *fl_nc, *fl_pv, *fl_nv;
    int *sl_pc_s, *sl_nc_s, *sl_pv_s, *sl_nv_s;
    float *sl_pc_w, *sl_nc_w, *sl_pv_w, *sl_nv_w;
    unsigned char *img_mlp, *img_cu, *img_vu;
    cudaGetSymbolAddress(&p, g_t_pv2c); t_pv2c = (unsigned short*)p;
    cudaGetSymbolAddress(&p, g_t_nv2c); t_nv2c = (unsigned short*)p;
    cudaGetSymbolAddress(&p, g_t_pc2v); t_pc2v = (unsigned short*)p;
    cudaGetSymbolAddress(&p, g_t_nc2v); t_nc2v = (unsigned short*)p;
    cudaGetSymbolAddress(&p, g_agg_c);  agg_c  = (unsigned short*)p;
    cudaGetSymbolAddress(&p, g_agg_v);  agg_v  = (unsigned short*)p;
    cudaGetSymbolAddress(&p, g_degi_pv); degi_pv = (int*)p;
    cudaGetSymbolAddress(&p, g_degi_nv); degi_nv = (int*)p;
    cudaGetSymbolAddress(&p, g_degi_pc); degi_pc = (int*)p;
    cudaGetSymbolAddress(&p, g_degi_nc); degi_nc = (int*)p;
    cudaGetSymbolAddress(&p, g_rp_pc); rp_pc = (int*)p;
    cudaGetSymbolAddress(&p, g_rp_nc); rp_nc = (int*)p;
    cudaGetSymbolAddress(&p, g_rp_pv); rp_pv = (int*)p;
    cudaGetSymbolAddress(&p, g_rp_nv); rp_nv = (int*)p;
    cudaGetSymbolAddress(&p, g_fl_pc); fl_pc = (int*)p;
    cudaGetSymbolAddress(&p, g_fl_nc); fl_nc = (int*)p;
    cudaGetSymbolAddress(&p, g_fl_pv); fl_pv = (int*)p;
    cudaGetSymbolAddress(&p, g_fl_nv); fl_nv = (int*)p;
    cudaGetSymbolAddress(&p, g_sl_pc_src); sl_pc_s = (int*)p;
    cudaGetSymbolAddress(&p, g_sl_nc_src); sl_nc_s = (int*)p;
    cudaGetSymbolAddress(&p, g_sl_pv_src); sl_pv_s = (int*)p;
    cudaGetSymbolAddress(&p, g_sl_nv_src); sl_nv_s = (int*)p;
    cudaGetSymbolAddress(&p, g_sl_pc_w); sl_pc_w = (float*)p;
    cudaGetSymbolAddress(&p, g_sl_nc_w); sl_nc_w = (float*)p;
    cudaGetSymbolAddress(&p, g_sl_pv_w); sl_pv_w = (float*)p;
    cudaGetSymbolAddress(&p, g_sl_nv_w); sl_nv_w = (float*)p;
    cudaGetSymbolAddress(&p, g_wimg_mlp); img_mlp = (unsigned char*)p;
    cudaGetSymbolAddress(&p, g_wimg_cu);  img_cu  = (unsigned char*)p;
    cudaGetSymbolAddress(&p, g_wimg_vu);  img_vu  = (unsigned char*)p;

    unsigned short* agg_c_p = agg_c;
    unsigned short* agg_c_n = agg_c + (size_t)CMAX * D;
    unsigned short* agg_v_p = agg_v;
    unsigned short* agg_v_n = agg_v + (size_t)VMAX * D;

    float* outv = (float*)d_out;
    float* outc = outv + (size_t)4 * V * D;

    int sms = 148;
    cudaDeviceGetAttribute(&sms, cudaDevAttrMultiProcessorCount, 0);

    cudaFuncSetAttribute(mlp2_mma_kernel,
                         cudaFuncAttributeMaxDynamicSharedMemorySize, MS_TOT);
    cudaFuncSetAttribute(update_mma_kernel,
                         cudaFuncAttributeMaxDynamicSharedMemorySize, US_TOT);

    // ---- prep: degrees -> scan -> CSR fill; weight images ----
    cudaMemsetAsync(degi_pv, 0, (size_t)V * sizeof(int));
    cudaMemsetAsync(degi_nv, 0, (size_t)V * sizeof(int));
    cudaMemsetAsync(degi_pc, 0, (size_t)C * sizeof(int));
    cudaMemsetAsync(degi_nc, 0, (size_t)C * sizeof(int));
    cudaMemsetAsync(fl_pc, 0, (size_t)C * sizeof(int));
    cudaMemsetAsync(fl_nc, 0, (size_t)C * sizeof(int));
    cudaMemsetAsync(fl_pv, 0, (size_t)V * sizeof(int));
    cudaMemsetAsync(fl_nv, 0, (size_t)V * sizeof(int));
    {
        int blk = (2 * Eh + NT - 1) / NT;
        degree_kernel<<<blk, NT>>>(v_edge, c_edge, p_edge, n_edge, Eh);
        scan4_kernel<<<4, 1024>>>(V, C);
        fill_kernel<<<blk, NT>>>(v_edge, c_edge, p_edge, n_edge, Eh);
    }
    for (int i = 0; i < 4; i++)
        wconv_mlp_kernel<<<128, 256>>>(Wm[i], img_mlp + (size_t)i * 2 * 32768);
    wconv_upd_kernel<<<192, 256>>>(cuW, img_cu);
    wconv_upd_kernel<<<192, 256>>>(vuW, img_vu);

    cudaMemcpyAsync(outv, v0, (size_t)V * D * sizeof(float), cudaMemcpyDeviceToDevice);
    cudaMemcpyAsync(outc, c0, (size_t)C * D * sizeof(float), cudaMemcpyDeviceToDevice);

    const int gthC = (int)(((long)C * 16 + NT - 1) / NT);
    const int gthV = (int)(((long)V * 16 + NT - 1) / NT);

    for (int t = 0; t < 3; t++) {
        const float* vin = outv + (size_t)t * V * D;
        const float* cin = outc + (size_t)t * C * D;
        float* vout = outv + (size_t)(t + 1) * V * D;
        float* cout = outc + (size_t)(t + 1) * C * D;

        mlp2_mma_kernel<<<2 * sms, NT, MS_TOT>>>(
            vin, (const uint4*)(img_mlp + 0 * 2 * 32768), Bm[0], t_pv2c, V);
        mlp2_mma_kernel<<<2 * sms, NT, MS_TOT>>>(
            vin, (const uint4*)(img_mlp + 1 * 2 * 32768), Bm[1], t_nv2c, V);
        mlp2_mma_kernel<<<2 * sms, NT, MS_TOT>>>(
            cin, (const uint4*)(img_mlp + 2 * 2 * 32768), Bm[2], t_pc2v, C);
        mlp2_mma_kernel<<<2 * sms, NT, MS_TOT>>>(
            cin, (const uint4*)(img_mlp + 3 * 2 * 32768), Bm[3], t_nc2v, C);

        gather_kernel<<<gthC, NT>>>(t_pv2c, agg_c_p, rp_pc, sl_pc_s, sl_pc_w, C);
        gather_kernel<<<gthC, NT>>>(t_nv2c, agg_c_n, rp_nc, sl_nc_s, sl_nc_w, C);
        gather_kernel<<<gthV, NT>>>(t_pc2v, agg_v_p, rp_pv, sl_pv_s, sl_pv_w, V);
        gather_kernel<<<gthV, NT>>>(t_nc2v, agg_v_n, rp_nv, sl_nv_s, sl_nv_w, V);

        update_mma_kernel<<<2 * sms, NT, US_TOT>>>(
            cin, agg_c_p, agg_c_n, (const uint4*)img_cu, cub, cout, C);
        update_mma_kernel<<<2 * sms, NT, US_TOT>>>(
            vin, agg_v_p, agg_v_n, (const uint4*)img_vu, vub, vout, V);
    }
}

// round 10
// speedup vs baseline: 3.9564x; 1.0689x over previous
#include <cuda_runtime.h>
#include <cuda_fp16.h>
#include <cstdint>

// ---------------------------------------------------------------------------
// GCN_VCG, round 10: launch fusion.
//  Per iteration: 1 fused MLP kernel (4 segments), 1 fused gather kernel
//  (4 CSR sets), 1 fused update kernel (2 segments). Same math as R9
//  (fp16 single-pass mma.sync GEMMs, fp16 intermediates, CSR gather).
// ---------------------------------------------------------------------------

#define D        128
#define NT       256
#define VMAX     50000
#define CMAX     210000
#define EHMAX    315000

// ------------------------- scratch (no runtime alloc) ----------------------
__device__ unsigned short g_t_pv2c[(size_t)VMAX * D];
__device__ unsigned short g_t_nv2c[(size_t)VMAX * D];
__device__ unsigned short g_t_pc2v[(size_t)CMAX * D];
__device__ unsigned short g_t_nc2v[(size_t)CMAX * D];
__device__ unsigned short g_agg_c[2][(size_t)CMAX * D];
__device__ unsigned short g_agg_v[2][(size_t)VMAX * D];
__device__ unsigned char g_wimg_mlp[4][2 * 32768];
__device__ unsigned char g_wimg_cu[3 * 32768];
__device__ unsigned char g_wimg_vu[3 * 32768];
__device__ int   g_degi_pv[VMAX], g_degi_nv[VMAX];
__device__ int   g_degi_pc[CMAX], g_degi_nc[CMAX];
__device__ int   g_rp_pc[CMAX + 1], g_rp_nc[CMAX + 1];
__device__ int   g_rp_pv[VMAX + 1], g_rp_nv[VMAX + 1];
__device__ int   g_fl_pc[CMAX], g_fl_nc[CMAX], g_fl_pv[VMAX], g_fl_nv[VMAX];
__device__ int   g_sl_pc_src[EHMAX], g_sl_nc_src[EHMAX];
__device__ int   g_sl_pv_src[EHMAX], g_sl_nv_src[EHMAX];
__device__ float g_sl_pc_w[EHMAX], g_sl_nc_w[EHMAX];
__device__ float g_sl_pv_w[EHMAX], g_sl_nv_w[EHMAX];

// ------------------------------ helpers ------------------------------------
__device__ __forceinline__ uint32_t smem_u32(const void* p) {
    uint32_t a;
    asm("{ .reg .u64 t; cvta.to.shared.u64 t, %1; cvt.u32.u64 %0, t; }"
        : "=r"(a) : "l"(p));
    return a;
}

__device__ __host__ __forceinline__ uint32_t swz(int r, int c) {
    return ((uint32_t)r << 8) + ((uint32_t)(((c >> 3) ^ (r & 7)) & 15) << 4)
         + ((uint32_t)(c & 7) << 1);
}

__device__ __forceinline__ uint32_t pack_h2(float a, float b) {
    __half2 h = __floats2half2_rn(a, b);
    return *reinterpret_cast<uint32_t*>(&h);
}

__device__ __forceinline__ float2 unpack_h2(uint32_t u) {
    return __half22float2(*reinterpret_cast<__half2*>(&u));
}

__device__ __forceinline__ void ldm4(uint32_t addr, uint32_t& d0, uint32_t& d1,
                                     uint32_t& d2, uint32_t& d3) {
    asm volatile("ldmatrix.sync.aligned.m8n8.x4.shared.b16 {%0,%1,%2,%3}, [%4];"
                 : "=r"(d0), "=r"(d1), "=r"(d2), "=r"(d3) : "r"(addr));
}

__device__ __forceinline__ void mma16816(float* c, const uint32_t* a,
                                         const uint32_t* b) {
    asm volatile(
        "mma.sync.aligned.m16n8k16.row.col.f32.f16.f16.f32 "
        "{%0,%1,%2,%3}, {%4,%5,%6,%7}, {%8,%9}, {%0,%1,%2,%3};"
        : "+f"(c[0]), "+f"(c[1]), "+f"(c[2]), "+f"(c[3])
        : "r"(a[0]), "r"(a[1]), "r"(a[2]), "r"(a[3]), "r"(b[0]), "r"(b[1]));
}

__device__ __forceinline__ void cp16(uint32_t saddr, const void* g, bool pred) {
    int sz = pred ? 16 : 0;
    asm volatile("cp.async.cg.shared.global [%0], [%1], 16, %2;"
                 :: "r"(saddr), "l"(g), "r"(sz));
}
#define CP_COMMIT() asm volatile("cp.async.commit_group;" ::: "memory")
#define CP_WAIT0()  asm volatile("cp.async.wait_group 0;" ::: "memory")

__device__ __forceinline__ void gemm_pass64(uint32_t sA, uint32_t sW,
                                            float acc[2][4][4],
                                            int wm, int wn, int lane) {
#pragma unroll
    for (int ks = 0; ks < 8; ks++) {
        const int kc = ks * 2;
        uint32_t a[2][4];
#pragma unroll
        for (int s = 0; s < 2; s++) {
            int row = wm * 32 + s * 16 + (lane & 7) + ((lane >> 3) & 1) * 8;
            int chunk = ((kc + (lane >> 4)) ^ (row & 7)) & 15;
            ldm4(sA + row * 256 + chunk * 16, a[s][0], a[s][1], a[s][2], a[s][3]);
        }
        uint32_t b[4][2];
#pragma unroll
        for (int p = 0; p < 2; p++) {
            int row = wn * 32 + p * 16 + (lane & 7) + (lane >> 4) * 8;
            int chunk = ((kc + ((lane >> 3) & 1)) ^ (row & 7)) & 15;
            ldm4(sW + row * 256 + chunk * 16,
                 b[2 * p][0], b[2 * p][1], b[2 * p + 1][0], b[2 * p + 1][1]);
        }
#pragma unroll
        for (int s = 0; s < 2; s++)
#pragma unroll
            for (int nt = 0; nt < 4; nt++)
                mma16816(acc[s][nt], a[s], b[nt]);
    }
}

__device__ __forceinline__ void zero_acc(float acc[2][4][4]) {
#pragma unroll
    for (int s = 0; s < 2; s++)
#pragma unroll
        for (int nt = 0; nt < 4; nt++)
#pragma unroll
            for (int j = 0; j < 4; j++) acc[s][nt][j] = 0.f;
}

__device__ __forceinline__ void load64_f32(const float* __restrict__ X,
                                           char* sm, uint32_t sa,
                                           int row0, int N, int tid) {
#pragma unroll
    for (int i = tid; i < 2048; i += NT) {
        int r = i >> 5, c4 = i & 31, g = row0 + r;
        float4 x = make_float4(0.f, 0.f, 0.f, 0.f);
        if (g < N) x = *reinterpret_cast<const float4*>(X + (size_t)g * D + c4 * 4);
        uint2 h = make_uint2(pack_h2(x.x, x.y), pack_h2(x.z, x.w));
        *reinterpret_cast<uint2*>(sm + sa + swz(r, c4 * 4)) = h;
    }
}

__device__ __forceinline__ void load64_f16(const unsigned short* __restrict__ X,
                                           char* sm, uint32_t sa,
                                           int row0, int N, int tid) {
#pragma unroll
    for (int i = tid; i < 2048; i += NT) {
        int r = i >> 5, c4 = i & 31, g = row0 + r;
        uint2 h = make_uint2(0u, 0u);
        if (g < N) h = *reinterpret_cast<const uint2*>(X + (size_t)g * D + c4 * 4);
        *reinterpret_cast<uint2*>(sm + sa + swz(r, c4 * 4)) = h;
    }
}

// --------------------------- fused MLP kernel -------------------------------
// 4 segments: {vin->y0, vin->y1, cin->y2, cin->y3}; CTAs split proportionally.
// smem: [W0 32KB][W1 32KB][A 16KB][bias 1KB] = 82944 B -> 2 CTAs/SM
#define MS_W    0
#define MS_A    65536
#define MS_B    81920
#define MS_TOT  82944

extern "C" __global__ void __launch_bounds__(NT, 2)
mlp4_kernel(const float* __restrict__ vin, const float* __restrict__ cin,
            const uint4* __restrict__ img, // 4 images, stride 4096 uint4
            const float* __restrict__ b0, const float* __restrict__ b1,
            const float* __restrict__ b2, const float* __restrict__ b3,
            unsigned short* __restrict__ y0, unsigned short* __restrict__ y1,
            unsigned short* __restrict__ y2, unsigned short* __restrict__ y3,
            int V, int C) {
    extern __shared__ char sm[];
    const uint32_t sb = smem_u32(sm);
    const int tid = threadIdx.x, wid = tid >> 5, lane = tid & 31;
    const int wm = wid >> 2, wn = wid & 3;
    float* bs = reinterpret_cast<float*>(sm + MS_B);

    // ---- segment assignment ----
    const int tV = (V + 63) >> 6, tC = (C + 63) >> 6;
    const long T = 2L * tV + 2L * tC;
    const int G = gridDim.x;
    int cV = (int)((long)G * tV / T); if (cV < 1) cV = 1;
    int cC = (G - 2 * cV) >> 1; if (cC < 1) cC = 1;
    const int bnd1 = cV, bnd2 = 2 * cV, bnd3 = 2 * cV + cC;

    int seg, start, stride, tiles, N;
    const float* X; const float* bias; unsigned short* Y;
    const int b = blockIdx.x;
    if (b < bnd1)      { seg = 0; start = b;        stride = cV;     }
    else if (b < bnd2) { seg = 1; start = b - bnd1; stride = cV;     }
    else if (b < bnd3) { seg = 2; start = b - bnd2; stride = cC;     }
    else               { seg = 3; start = b - bnd3; stride = G - bnd3; }
    if (seg < 2) { X = vin; N = V; tiles = tV; }
    else         { X = cin; N = C; tiles = tC; }
    bias = (seg == 0) ? b0 : (seg == 1) ? b1 : (seg == 2) ? b2 : b3;
    Y    = (seg == 0) ? y0 : (seg == 1) ? y1 : (seg == 2) ? y2 : y3;
    const uint4* Wimg = img + (size_t)seg * 4096;

#pragma unroll 4
    for (int i = tid; i < 4096; i += NT)      // 64KB resident weights
        cp16(sb + MS_W + i * 16, Wimg + i, true);
    if (tid < 2 * D) bs[tid] = bias[tid];
    CP_COMMIT();
    CP_WAIT0();
    __syncthreads();

    for (int t = start; t < tiles; t += stride) {
        const int row0 = t * 64;
        load64_f32(X, sm, MS_A, row0, N, tid);
        __syncthreads();

        float acc[2][4][4];
        zero_acc(acc);
        gemm_pass64(sb + MS_A, sb + MS_W, acc, wm, wn, lane);
        __syncthreads();

#pragma unroll
        for (int s = 0; s < 2; s++) {
#pragma unroll
            for (int nt = 0; nt < 4; nt++) {
                int m = wm * 32 + s * 16 + (lane >> 2);
                int n = wn * 32 + nt * 8 + (lane & 3) * 2;
                float c0 = bs[n], c1 = bs[n + 1];
                uint32_t h0 = pack_h2(fmaxf(acc[s][nt][0] + c0, 0.f),
                                      fmaxf(acc[s][nt][1] + c1, 0.f));
                uint32_t h1 = pack_h2(fmaxf(acc[s][nt][2] + c0, 0.f),
                                      fmaxf(acc[s][nt][3] + c1, 0.f));
                *reinterpret_cast<uint32_t*>(sm + MS_A + swz(m, n)) = h0;
                *reinterpret_cast<uint32_t*>(sm + MS_A + swz(m + 8, n)) = h1;
            }
        }
        __syncthreads();

        zero_acc(acc);
        gemm_pass64(sb + MS_A, sb + MS_W + 32768, acc, wm, wn, lane);

#pragma unroll
        for (int s = 0; s < 2; s++) {
#pragma unroll
            for (int nt = 0; nt < 4; nt++) {
                int m = wm * 32 + s * 16 + (lane >> 2);
                int n = wn * 32 + nt * 8 + (lane & 3) * 2;
                float c0 = bs[D + n], c1 = bs[D + n + 1];
                int g0 = row0 + m, g1 = row0 + m + 8;
                if (g0 < N)
                    *reinterpret_cast<uint32_t*>(Y + (size_t)g0 * D + n) =
                        pack_h2(acc[s][nt][0] + c0, acc[s][nt][1] + c1);
                if (g1 < N)
                    *reinterpret_cast<uint32_t*>(Y + (size_t)g1 * D + n) =
                        pack_h2(acc[s][nt][2] + c0, acc[s][nt][3] + c1);
            }
        }
        __syncthreads();
    }
}

// --------------------------- fused update kernel ----------------------------
// 2 segments: {c-update (C rows), v-update (V rows)}.
// smem: [W x3 96KB][A 16KB][bias 512B] = 115200 B
#define US_W    0
#define US_A    98304
#define US_B    114688
#define US_TOT  115200

extern "C" __global__ void __launch_bounds__(NT, 1)
update2_kernel(const float* __restrict__ cin, const float* __restrict__ vin,
               const unsigned short* __restrict__ aggc_p,
               const unsigned short* __restrict__ aggc_n,
               const unsigned short* __restrict__ aggv_p,
               const unsigned short* __restrict__ aggv_n,
               const uint4* __restrict__ cuImg, const uint4* __restrict__ vuImg,
               const float* __restrict__ cub, const float* __restrict__ vub,
               float* __restrict__ cout, float* __restrict__ vout,
               int V, int C) {
    extern __shared__ char sm[];
    const uint32_t sb = smem_u32(sm);
    const int tid = threadIdx.x, wid = tid >> 5, lane = tid & 31;
    const int wm = wid >> 2, wn = wid & 3;
    float* bs = reinterpret_cast<float*>(sm + US_B);

    const int tV = (V + 63) >> 6, tC = (C + 63) >> 6;
    const int G = gridDim.x;
    int cC = (int)((long)G * tC / (tC + tV)); if (cC < 1) cC = 1;
    if (cC > G - 1) cC = G - 1;

    int start, stride, tiles, N;
    const float* X0; const unsigned short *X1, *X2;
    const uint4* Wimg; const float* bias; float* Y;
    const int b = blockIdx.x;
    if (b < cC) {
        start = b; stride = cC; tiles = tC; N = C;
        X0 = cin; X1 = aggc_p; X2 = aggc_n;
        Wimg = cuImg; bias = cub; Y = cout;
    } else {
        start = b - cC; stride = G - cC; tiles = tV; N = V;
        X0 = vin; X1 = aggv_p; X2 = aggv_n;
        Wimg = vuImg; bias = vub; Y = vout;
    }

#pragma unroll 4
    for (int i = tid; i < 6144; i += NT)      // 96KB resident weights
        cp16(sb + US_W + i * 16, Wimg + i, true);
    if (tid < D) bs[tid] = bias[tid];
    CP_COMMIT();
    CP_WAIT0();
    __syncthreads();

    for (int t = start; t < tiles; t += stride) {
        const int row0 = t * 64;
        float acc[2][4][4];
        zero_acc(acc);

        load64_f32(X0, sm, US_A, row0, N, tid);
        __syncthreads();
        gemm_pass64(sb + US_A, sb + US_W, acc, wm, wn, lane);
        __syncthreads();

        load64_f16(X1, sm, US_A, row0, N, tid);
        __syncthreads();
        gemm_pass64(sb + US_A, sb + US_W + 32768, acc, wm, wn, lane);
        __syncthreads();

        load64_f16(X2, sm, US_A, row0, N, tid);
        __syncthreads();
        gemm_pass64(sb + US_A, sb + US_W + 65536, acc, wm, wn, lane);
        __syncthreads();

#pragma unroll
        for (int s = 0; s < 2; s++) {
#pragma unroll
            for (int nt = 0; nt < 4; nt++) {
                int m = wm * 32 + s * 16 + (lane >> 2);
                int n = wn * 32 + nt * 8 + (lane & 3) * 2;
                float c0 = bs[n], c1 = bs[n + 1];
                int g0 = row0 + m, g1 = row0 + m + 8;
                if (g0 < N) {
                    float2 o = make_float2(acc[s][nt][0] + c0, acc[s][nt][1] + c1);
                    *reinterpret_cast<float2*>(Y + (size_t)g0 * D + n) = o;
                }
                if (g1 < N) {
                    float2 o = make_float2(acc[s][nt][2] + c0, acc[s][nt][3] + c1);
                    *reinterpret_cast<float2*>(Y + (size_t)g1 * D + n) = o;
                }
            }
        }
    }
}

// ----------------------- weight image conversion ----------------------------
extern "C" __global__ void wconv_mlp_kernel(const float* __restrict__ W,
                                            unsigned char* __restrict__ img) {
    int t = blockIdx.x * blockDim.x + threadIdx.x;
    if (t >= 2 * 128 * 128) return;
    int l = t >> 14, k = (t >> 7) & 127, n = t & 127;
    __half h = __float2half_rn(W[t]);
    *reinterpret_cast<__half*>(img + (size_t)l * 32768 + swz(n, k)) = h;
}

extern "C" __global__ void wconv_upd_kernel(const float* __restrict__ W,
                                            unsigned char* __restrict__ img) {
    int t = blockIdx.x * blockDim.x + threadIdx.x;
    if (t >= 384 * 128) return;
    int k = t >> 7, n = t & 127;
    int s = k >> 7, kl = k & 127;
    __half h = __float2half_rn(W[t]);
    *reinterpret_cast<__half*>(img + (size_t)s * 32768 + swz(n, kl)) = h;
}

// ------------------------------ CSR build -----------------------------------
extern "C" __global__ void degree_kernel(const int* __restrict__ vE,
                                         const int* __restrict__ cE,
                                         const int* __restrict__ pE,
                                         const int* __restrict__ nE, int Eh) {
    int t = blockIdx.x * blockDim.x + threadIdx.x;
    if (t < Eh) {
        int e = pE[t];
        atomicAdd(&g_degi_pv[vE[e]], 1);
        atomicAdd(&g_degi_pc[cE[e]], 1);
    } else if (t < 2 * Eh) {
        int e = nE[t - Eh];
        atomicAdd(&g_degi_nv[vE[e]], 1);
        atomicAdd(&g_degi_nc[cE[e]], 1);
    }
}

extern "C" __global__ void __launch_bounds__(1024)
scan4_kernel(int V, int C) {
    const int* d; int* r; int n;
    switch (blockIdx.x) {
        case 0:  d = g_degi_pc; r = g_rp_pc; n = C; break;
        case 1:  d = g_degi_nc; r = g_rp_nc; n = C; break;
        case 2:  d = g_degi_pv; r = g_rp_pv; n = V; break;
        default: d = g_degi_nv; r = g_rp_nv; n = V; break;
    }
    __shared__ int wsum[32];
    __shared__ int sh_carry, sh_total;
    int tid = threadIdx.x, lane = tid & 31, wid = tid >> 5;
    if (tid == 0) sh_carry = 0;
    __syncthreads();
    for (int base = 0; base < n; base += 1024) {
        int i = base + tid;
        int v = (i < n) ? d[i] : 0;
        int incl = v;
#pragma unroll
        for (int o = 1; o < 32; o <<= 1) {
            int x = __shfl_up_sync(0xffffffffu, incl, o);
            if (lane >= o) incl += x;
        }
        if (lane == 31) wsum[wid] = incl;
        __syncthreads();
        if (tid < 32) {
            int s = wsum[tid], ip = s;
#pragma unroll
            for (int o = 1; o < 32; o <<= 1) {
                int x = __shfl_up_sync(0xffffffffu, ip, o);
                if (tid >= o) ip += x;
            }
            wsum[tid] = ip - s;
            if (tid == 31) sh_total = ip;
        }
        __syncthreads();
        if (i < n) r[i] = sh_carry + wsum[wid] + incl - v;
        __syncthreads();
        if (tid == 0) sh_carry += sh_total;
        __syncthreads();
    }
    if (tid == 0) r[n] = sh_carry;
}

extern "C" __global__ void fill_kernel(const int* __restrict__ vE,
                                       const int* __restrict__ cE,
                                       const int* __restrict__ pE,
                                       const int* __restrict__ nE, int Eh) {
    int t = blockIdx.x * blockDim.x + threadIdx.x;
    if (t < Eh) {
        int e = pE[t];
        int v = vE[e], c = cE[e];
        float inv = rsqrtf((float)max(g_degi_pv[v], 1) * (float)max(g_degi_pc[c], 1));
        int pos = g_rp_pc[c] + atomicAdd(&g_fl_pc[c], 1);
        g_sl_pc_src[pos] = v;
        g_sl_pc_w[pos] = inv;
        int pos2 = g_rp_pv[v] + atomicAdd(&g_fl_pv[v], 1);
        g_sl_pv_src[pos2] = c;
        g_sl_pv_w[pos2] = inv;
    } else if (t < 2 * Eh) {
        int e = nE[t - Eh];
        int v = vE[e], c = cE[e];
        float inv = rsqrtf((float)max(g_degi_nv[v], 1) * (float)max(g_degi_nc[c], 1));
        int pos = g_rp_nc[c] + atomicAdd(&g_fl_nc[c], 1);
        g_sl_nc_src[pos] = v;
        g_sl_nc_w[pos] = inv;
        int pos2 = g_rp_nv[v] + atomicAdd(&g_fl_nv[v], 1);
        g_sl_nv_src[pos2] = c;
        g_sl_nv_w[pos2] = inv;
    }
}

// ------------------------- fused CSR gather (x4) ----------------------------
// 16-lane group per destination node across all 4 gathers:
// groups [0,C): pc, [C,2C): nc, [2C,2C+V): pv, [2C+V, 2C+2V): nv
extern "C" __global__ void __launch_bounds__(NT)
gather4_kernel(const unsigned short* __restrict__ t_pv2c,
               const unsigned short* __restrict__ t_nv2c,
               const unsigned short* __restrict__ t_pc2v,
               const unsigned short* __restrict__ t_nc2v,
               unsigned short* __restrict__ aggc_p,
               unsigned short* __restrict__ aggc_n,
               unsigned short* __restrict__ aggv_p,
               unsigned short* __restrict__ aggv_n,
               int V, int C) {
    long t = (long)blockIdx.x * blockDim.x + threadIdx.x;
    int gidx = (int)(t >> 4), sub = (int)(t & 15);
    const unsigned short* src; unsigned short* dst;
    const int* rp; const int* sl; const float* wv;
    int node;
    if (gidx < C) {
        node = gidx; src = t_pv2c; dst = aggc_p;
        rp = g_rp_pc; sl = g_sl_pc_src; wv = g_sl_pc_w;
    } else if (gidx < 2 * C) {
        node = gidx - C; src = t_nv2c; dst = aggc_n;
        rp = g_rp_nc; sl = g_sl_nc_src; wv = g_sl_nc_w;
    } else if (gidx < 2 * C + V) {
        node = gidx - 2 * C; src = t_pc2v; dst = aggv_p;
        rp = g_rp_pv; sl = g_sl_pv_src; wv = g_sl_pv_w;
    } else if (gidx < 2 * C + 2 * V) {
        node = gidx - 2 * C - V; src = t_nc2v; dst = aggv_n;
        rp = g_rp_nv; sl = g_sl_nv_src; wv = g_sl_nv_w;
    } else return;

    int j = rp[node], end = rp[node + 1];
    float acc[8] = {0.f, 0.f, 0.f, 0.f, 0.f, 0.f, 0.f, 0.f};
    int s_next = 0; float w_next = 0.f;
    if (j < end) { s_next = __ldg(sl + j); w_next = __ldg(wv + j); }
    while (j < end) {
        int s = s_next; float w = w_next;
        j++;
        if (j < end) { s_next = __ldg(sl + j); w_next = __ldg(wv + j); }
        uint4 x = __ldg(reinterpret_cast<const uint4*>(src + (size_t)s * D) + sub);
        float2 f0 = unpack_h2(x.x), f1 = unpack_h2(x.y);
        float2 f2 = unpack_h2(x.z), f3 = unpack_h2(x.w);
        acc[0] = fmaf(w, f0.x, acc[0]); acc[1] = fmaf(w, f0.y, acc[1]);
        acc[2] = fmaf(w, f1.x, acc[2]); acc[3] = fmaf(w, f1.y, acc[3]);
        acc[4] = fmaf(w, f2.x, acc[4]); acc[5] = fmaf(w, f2.y, acc[5]);
        acc[6] = fmaf(w, f3.x, acc[6]); acc[7] = fmaf(w, f3.y, acc[7]);
    }
    uint4 o;
    o.x = pack_h2(acc[0], acc[1]);
    o.y = pack_h2(acc[2], acc[3]);
    o.z = pack_h2(acc[4], acc[5]);
    o.w = pack_h2(acc[6], acc[7]);
    reinterpret_cast<uint4*>(dst + (size_t)node * D)[sub] = o;
}

// -------------------------------- launch ------------------------------------
extern "C" void kernel_launch(void* const* d_in, const int* in_sizes, int n_in,
                              void* d_out, int out_size) {
    int base = (n_in >= 20) ? 2 : 0;
    const int*   v_edge = (const int*)d_in[base + 0];
    const int*   c_edge = (const int*)d_in[base + 1];
    const int*   p_edge = (const int*)d_in[base + 2];
    const int*   n_edge = (const int*)d_in[base + 3];
    const float* v0     = (const float*)d_in[base + 4];
    const float* c0     = (const float*)d_in[base + 5];
    const float *Wm[4], *Bm[4];
    for (int i = 0; i < 4; i++) {
        Wm[i] = (const float*)d_in[base + 6 + 2 * i];
        Bm[i] = (const float*)d_in[base + 7 + 2 * i];
    }
    const float* cuW = (const float*)d_in[base + 14];
    const float* cub = (const float*)d_in[base + 15];
    const float* vuW = (const float*)d_in[base + 16];
    const float* vub = (const float*)d_in[base + 17];

    const int Eh = in_sizes[base + 2];
    const int V  = in_sizes[base + 4] / D;
    const int C  = in_sizes[base + 5] / D;

    void* p;
    unsigned short *t_pv2c, *t_nv2c, *t_pc2v, *t_nc2v, *agg_c, *agg_v;
    int *degi_pv, *degi_nv, *degi_pc, *degi_nc;
    int *fl_pc, *fl_nc, *fl_pv, *fl_nv;
    unsigned char *img_mlp, *img_cu, *img_vu;
    cudaGetSymbolAddress(&p, g_t_pv2c); t_pv2c = (unsigned short*)p;
    cudaGetSymbolAddress(&p, g_t_nv2c); t_nv2c = (unsigned short*)p;
    cudaGetSymbolAddress(&p, g_t_pc2v); t_pc2v = (unsigned short*)p;
    cudaGetSymbolAddress(&p, g_t_nc2v); t_nc2v = (unsigned short*)p;
    cudaGetSymbolAddress(&p, g_agg_c);  agg_c  = (unsigned short*)p;
    cudaGetSymbolAddress(&p, g_agg_v);  agg_v  = (unsigned short*)p;
    cudaGetSymbolAddress(&p, g_degi_pv); degi_pv = (int*)p;
    cudaGetSymbolAddress(&p, g_degi_nv); degi_nv = (int*)p;
    cudaGetSymbolAddress(&p, g_degi_pc); degi_pc = (int*)p;
    cudaGetSymbolAddress(&p, g_degi_nc); degi_nc = (int*)p;
    cudaGetSymbolAddress(&p, g_fl_pc); fl_pc = (int*)p;
    cudaGetSymbolAddress(&p, g_fl_nc); fl_nc = (int*)p;
    cudaGetSymbolAddress(&p, g_fl_pv); fl_pv = (int*)p;
    cudaGetSymbolAddress(&p, g_fl_nv); fl_nv = (int*)p;
    cudaGetSymbolAddress(&p, g_wimg_mlp); img_mlp = (unsigned char*)p;
    cudaGetSymbolAddress(&p, g_wimg_cu);  img_cu  = (unsigned char*)p;
    cudaGetSymbolAddress(&p, g_wimg_vu);  img_vu  = (unsigned char*)p;

    unsigned short* agg_c_p = agg_c;
    unsigned short* agg_c_n = agg_c + (size_t)CMAX * D;
    unsigned short* agg_v_p = agg_v;
    unsigned short* agg_v_n = agg_v + (size_t)VMAX * D;

    float* outv = (float*)d_out;
    float* outc = outv + (size_t)4 * V * D;

    int sms = 148;
    cudaDeviceGetAttribute(&sms, cudaDevAttrMultiProcessorCount, 0);

    cudaFuncSetAttribute(mlp4_kernel,
                         cudaFuncAttributeMaxDynamicSharedMemorySize, MS_TOT);
    cudaFuncSetAttribute(update2_kernel,
                         cudaFuncAttributeMaxDynamicSharedMemorySize, US_TOT);

    // ---- prep: degrees -> scan -> CSR fill; weight images ----
    cudaMemsetAsync(degi_pv, 0, (size_t)V * sizeof(int));
    cudaMemsetAsync(degi_nv, 0, (size_t)V * sizeof(int));
    cudaMemsetAsync(degi_pc, 0, (size_t)C * sizeof(int));
    cudaMemsetAsync(degi_nc, 0, (size_t)C * sizeof(int));
    cudaMemsetAsync(fl_pc, 0, (size_t)C * sizeof(int));
    cudaMemsetAsync(fl_nc, 0, (size_t)C * sizeof(int));
    cudaMemsetAsync(fl_pv, 0, (size_t)V * sizeof(int));
    cudaMemsetAsync(fl_nv, 0, (size_t)V * sizeof(int));
    {
        int blk = (2 * Eh + NT - 1) / NT;
        degree_kernel<<<blk, NT>>>(v_edge, c_edge, p_edge, n_edge, Eh);
        scan4_kernel<<<4, 1024>>>(V, C);
        fill_kernel<<<blk, NT>>>(v_edge, c_edge, p_edge, n_edge, Eh);
    }
    for (int i = 0; i < 4; i++)
        wconv_mlp_kernel<<<128, 256>>>(Wm[i], img_mlp + (size_t)i * 2 * 32768);
    wconv_upd_kernel<<<192, 256>>>(cuW, img_cu);
    wconv_upd_kernel<<<192, 256>>>(vuW, img_vu);

    cudaMemcpyAsync(outv, v0, (size_t)V * D * sizeof(float), cudaMemcpyDeviceToDevice);
    cudaMemcpyAsync(outc, c0, (size_t)C * D * sizeof(float), cudaMemcpyDeviceToDevice);

    const long ggroups = 2L * C + 2L * V;
    const int gblocks = (int)((ggroups * 16 + NT - 1) / NT);

    for (int t = 0; t < 3; t++) {
        const float* vin = outv + (size_t)t * V * D;
        const float* cin = outc + (size_t)t * C * D;
        float* vout = outv + (size_t)(t + 1) * V * D;
        float* cout = outc + (size_t)(t + 1) * C * D;

        mlp4_kernel<<<2 * sms, NT, MS_TOT>>>(
            vin, cin, (const uint4*)img_mlp,
            Bm[0], Bm[1], Bm[2], Bm[3],
            t_pv2c, t_nv2c, t_pc2v, t_nc2v, V, C);

        gather4_kernel<<<gblocks, NT>>>(
            t_pv2c, t_nv2c, t_pc2v, t_nc2v,
            agg_c_p, agg_c_n, agg_v_p, agg_v_n, V, C);

        update2_kernel<<<sms, NT, US_TOT>>>(
            cin, vin, agg_c_p, agg_c_n, agg_v_p, agg_v_n,
            (const uint4*)img_cu, (const uint4*)img_vu,
            cub, vub, cout, vout, V, C);
    }
}